// round 3
// baseline (speedup 1.0000x reference)
#include <cuda_runtime.h>
#include <cuda_fp16.h>
#include <math.h>
#include <stdint.h>

#define BATCH  2
#define SEQ    2048
#define DMODEL 2048
#define NH     16
#define NKV    8
#define HD     128

// ---------------------------------------------------------------------------
// Scratch (device globals; no allocation allowed)
// ---------------------------------------------------------------------------
__device__ __half g_q[(size_t)BATCH * NH  * SEQ * HD];   // [b][h][s][d], rope'd + scaled
__device__ __half g_k[(size_t)BATCH * NKV * SEQ * HD];   // [b][kv][s][d], rope'd
__device__ __half g_v[(size_t)BATCH * NKV * SEQ * HD];   // [b][kv][s][d]
__device__ float  g_o[(size_t)BATCH * SEQ * NH * HD];    // [b*S + s][h*hd + d] fp32
__device__ float  g_cos[SEQ * (HD / 2)];
__device__ float  g_sin[SEQ * (HD / 2)];

// ---------------------------------------------------------------------------
// Helpers
// ---------------------------------------------------------------------------
__device__ __forceinline__ uint32_t pack_half2(float a, float b) {
  __half2 h = __floats2half2_rn(a, b);
  return *reinterpret_cast<uint32_t*>(&h);
}

// mma.sync m16n8k16 fp16 -> fp32
#define MMA_16816(C, A, B0, B1)                                              \
  asm volatile(                                                              \
      "mma.sync.aligned.m16n8k16.row.col.f32.f16.f16.f32 "                   \
      "{%0,%1,%2,%3}, {%4,%5,%6,%7}, {%8,%9}, {%0,%1,%2,%3};\n"              \
      : "+f"((C)[0]), "+f"((C)[1]), "+f"((C)[2]), "+f"((C)[3])               \
      : "r"((A)[0]), "r"((A)[1]), "r"((A)[2]), "r"((A)[3]),                  \
        "r"(B0), "r"(B1))

#define LDSM_X4(R0, R1, R2, R3, ADDR)                                        \
  asm volatile(                                                              \
      "ldmatrix.sync.aligned.m8n8.x4.shared.b16 {%0,%1,%2,%3}, [%4];\n"      \
      : "=r"(R0), "=r"(R1), "=r"(R2), "=r"(R3) : "r"(ADDR))

// ---------------------------------------------------------------------------
// RoPE tables
// ---------------------------------------------------------------------------
__global__ void rope_init_kernel() {
  int idx = blockIdx.x * blockDim.x + threadIdx.x;
  if (idx < SEQ * (HD / 2)) {
    int s = idx >> 6;
    int i = idx & 63;
    float inv = (float)pow(10000.0, -(double)(2 * i) / (double)HD);
    float a = (float)s * inv;
    g_cos[idx] = cosf(a);
    g_sin[idx] = sinf(a);
  }
}

// ---------------------------------------------------------------------------
// Split-fp16 GEMM: C[4096, N] = A[4096, 2048] @ W[2048, N], both fp32 inputs.
// A = Ah + Al, W = Wh + Wl; C = AhWh + AhWl + AlWh (3-mma split, ~fp32 acc).
// Block tile 128x128, BK=32, 256 threads = 8 warps in 4(M) x 2(N) grid,
// warp tile 32x64. ldmatrix.x4 fragment loads. Register-staged LDG pipeline.
// MODE 0: Q (rope + 1/sqrt(hd) -> g_q fp16)   MODE 1: K (rope -> g_k fp16)
// MODE 2: V (-> g_v fp16)                     MODE 3: out proj (-> out fp32)
// ---------------------------------------------------------------------------
template <int MODE>
__global__ __launch_bounds__(256) void gemm_split_kernel(
    const float* __restrict__ A, const float* __restrict__ W,
    float* __restrict__ out, int N) {
  __shared__ __align__(16) __half Ah[128][40];
  __shared__ __align__(16) __half Al[128][40];
  __shared__ __align__(16) __half Bh[128][40];
  __shared__ __align__(16) __half Bl[128][40];

  const int tid  = threadIdx.x;
  const int wid  = tid >> 5;
  const int lane = tid & 31;
  const int wm   = wid >> 1;     // 0..3
  const int wn   = wid & 1;      // 0..1
  const int g    = lane >> 2;
  const int q4   = lane & 3;
  const int m0   = blockIdx.y * 128;
  const int n0   = blockIdx.x * 128;

  // ldmatrix base addresses (shared-space byte addresses)
  const uint32_t a_h = (uint32_t)__cvta_generic_to_shared(
      &Ah[wm * 32 + (lane & 15)][(lane >> 4) * 8]);
  const uint32_t a_l = (uint32_t)__cvta_generic_to_shared(
      &Al[wm * 32 + (lane & 15)][(lane >> 4) * 8]);
  const uint32_t b_h = (uint32_t)__cvta_generic_to_shared(
      &Bh[wn * 64 + (lane & 7) + ((lane & 16) >> 1)][(lane & 8)]);
  const uint32_t b_l = (uint32_t)__cvta_generic_to_shared(
      &Bl[wn * 64 + (lane & 7) + ((lane & 16) >> 1)][(lane & 8)]);

  float c[2][8][4];
#pragma unroll
  for (int mt = 0; mt < 2; mt++)
#pragma unroll
    for (int nt = 0; nt < 8; nt++)
#pragma unroll
      for (int j = 0; j < 4; j++) c[mt][nt][j] = 0.f;

  float4 aw[4], bw[4];

  auto load_tile = [&](int k0) {
#pragma unroll
    for (int j = 0; j < 4; j++) {
      int i = j * 256 + tid;
      aw[j] = *(const float4*)(A + (size_t)(m0 + (i >> 3)) * DMODEL + k0 + (i & 7) * 4);
      bw[j] = *(const float4*)(W + (size_t)(k0 + (i >> 5)) * N + n0 + (i & 31) * 4);
    }
  };

  auto convert_sts = [&]() {
#pragma unroll
    for (int j = 0; j < 4; j++) {
      int i   = j * 256 + tid;
      int row = i >> 3, f4 = i & 7;
      float ea[4] = {aw[j].x, aw[j].y, aw[j].z, aw[j].w};
      __half hh[4], hl[4];
#pragma unroll
      for (int t = 0; t < 4; t++) {
        hh[t] = __float2half_rn(ea[t]);
        hl[t] = __float2half_rn(ea[t] - __half2float(hh[t]));
      }
      *(__half2*)&Ah[row][f4 * 4]     = __halves2half2(hh[0], hh[1]);
      *(__half2*)&Ah[row][f4 * 4 + 2] = __halves2half2(hh[2], hh[3]);
      *(__half2*)&Al[row][f4 * 4]     = __halves2half2(hl[0], hl[1]);
      *(__half2*)&Al[row][f4 * 4 + 2] = __halves2half2(hl[2], hl[3]);

      int kk = i >> 5, fn = i & 31;
      float eb[4] = {bw[j].x, bw[j].y, bw[j].z, bw[j].w};
#pragma unroll
      for (int t = 0; t < 4; t++) {
        __half bhh = __float2half_rn(eb[t]);
        Bh[fn * 4 + t][kk] = bhh;
        Bl[fn * 4 + t][kk] = __float2half_rn(eb[t] - __half2float(bhh));
      }
    }
  };

  load_tile(0);
  convert_sts();
  __syncthreads();

  for (int k0 = 0; k0 < DMODEL; k0 += 32) {
    const bool nxt = (k0 + 32) < DMODEL;
    if (nxt) load_tile(k0 + 32);

#pragma unroll
    for (int kt = 0; kt < 2; kt++) {
      const uint32_t ko = kt * 32;  // 16 halves = 32 bytes
      uint32_t ah[2][4], al[2][4];
      LDSM_X4(ah[0][0], ah[0][1], ah[0][2], ah[0][3], a_h + ko);
      LDSM_X4(ah[1][0], ah[1][1], ah[1][2], ah[1][3], a_h + 1280 + ko);
      LDSM_X4(al[0][0], al[0][1], al[0][2], al[0][3], a_l + ko);
      LDSM_X4(al[1][0], al[1][1], al[1][2], al[1][3], a_l + 1280 + ko);

#pragma unroll
      for (int p = 0; p < 4; p++) {
        uint32_t bh[4], bl[4];
        LDSM_X4(bh[0], bh[1], bh[2], bh[3], b_h + p * 1280 + ko);
        LDSM_X4(bl[0], bl[1], bl[2], bl[3], b_l + p * 1280 + ko);
#pragma unroll
        for (int mt = 0; mt < 2; mt++) {
          MMA_16816(c[mt][2 * p],     ah[mt], bh[0], bh[1]);
          MMA_16816(c[mt][2 * p],     ah[mt], bl[0], bl[1]);
          MMA_16816(c[mt][2 * p],     al[mt], bh[0], bh[1]);
          MMA_16816(c[mt][2 * p + 1], ah[mt], bh[2], bh[3]);
          MMA_16816(c[mt][2 * p + 1], ah[mt], bl[2], bl[3]);
          MMA_16816(c[mt][2 * p + 1], al[mt], bh[2], bh[3]);
        }
      }
    }
    __syncthreads();
    if (nxt) {
      convert_sts();
      __syncthreads();
    }
  }

  // Epilogue
  const float qscale = 0.08838834764831845f;  // 1/sqrt(128)
#pragma unroll
  for (int mt = 0; mt < 2; mt++) {
#pragma unroll
    for (int nt = 0; nt < 8; nt++) {
      int col = n0 + wn * 64 + nt * 8 + q4 * 2;
      int row = m0 + wm * 32 + mt * 16 + g;
      if (MODE == 3) {
        *(float2*)&out[(size_t)row * DMODEL + col] =
            make_float2(c[mt][nt][0], c[mt][nt][1]);
        *(float2*)&out[(size_t)(row + 8) * DMODEL + col] =
            make_float2(c[mt][nt][2], c[mt][nt][3]);
      } else {
        int head = col >> 7;
        int d    = col & 127;
#pragma unroll
        for (int hh = 0; hh < 2; hh++) {
          int r = row + hh * 8;
          int b = r >> 11;
          int s = r & 2047;
          float v0 = c[mt][nt][hh * 2];
          float v1 = c[mt][nt][hh * 2 + 1];
          if (MODE != 2) {
            int i    = d >> 1;
            float cs = g_cos[s * 64 + i];
            float sn = g_sin[s * 64 + i];
            float r0 = v0 * cs - v1 * sn;
            float r1 = v0 * sn + v1 * cs;
            v0 = r0; v1 = r1;
            if (MODE == 0) { v0 *= qscale; v1 *= qscale; }
          }
          __half* dst;
          if (MODE == 0)
            dst = &g_q[(((size_t)(b * NH + head)) * SEQ + s) * HD + d];
          else if (MODE == 1)
            dst = &g_k[(((size_t)(b * NKV + head)) * SEQ + s) * HD + d];
          else
            dst = &g_v[(((size_t)(b * NKV + head)) * SEQ + s) * HD + d];
          *(__half2*)dst = __floats2half2_rn(v0, v1);
        }
      }
    }
  }
}

// ---------------------------------------------------------------------------
// Flash attention: one block = (qtile of 64 rows, head h, batch b)
// 128 threads = 4 warps x 16 rows. KV chunks of 64. Online softmax.
// ---------------------------------------------------------------------------
__global__ __launch_bounds__(128) void attn_kernel(const int* __restrict__ causal_flag) {
  __shared__ __align__(16) __half Ks[64][136];   // K chunk [seq][d] (also Q staging)
  __shared__ __align__(16) __half Vs[128][66];   // V chunk transposed [d][seq]

  const int tid  = threadIdx.x;
  const int wid  = tid >> 5;
  const int lane = tid & 31;
  const int g    = lane >> 2;
  const int q4   = lane & 3;
  const int qtile = blockIdx.x;
  const int h     = blockIdx.y;
  const int b     = blockIdx.z;
  const int kv    = h >> 1;            // G = NH/NKV = 2
  const int qbase = qtile * 64;
  const int causal = *causal_flag;

  const __half* qp = g_q + (((size_t)(b * NH + h)) * SEQ + qbase) * HD;
#pragma unroll
  for (int j = 0; j < 8; j++) {
    int i   = j * 128 + tid;
    int row = i >> 4;
    int seg = i & 15;
    *(uint4*)&Ks[row][seg * 8] = *(const uint4*)(qp + row * HD + seg * 8);
  }
  __syncthreads();
  uint32_t qa[8][4];
#pragma unroll
  for (int kt = 0; kt < 8; kt++) {
    int kb = kt * 16 + q4 * 2;
    qa[kt][0] = *(const uint32_t*)&Ks[wid * 16 + g][kb];
    qa[kt][1] = *(const uint32_t*)&Ks[wid * 16 + g + 8][kb];
    qa[kt][2] = *(const uint32_t*)&Ks[wid * 16 + g][kb + 8];
    qa[kt][3] = *(const uint32_t*)&Ks[wid * 16 + g + 8][kb + 8];
  }

  float o[16][4];
#pragma unroll
  for (int i = 0; i < 16; i++)
#pragma unroll
    for (int j = 0; j < 4; j++) o[i][j] = 0.f;
  float m0 = -1e30f, m1 = -1e30f, l0 = 0.f, l1 = 0.f;

  const int jend = causal ? (qbase + 64) : SEQ;
  const __half* kbp = g_k + ((size_t)(b * NKV + kv)) * SEQ * HD;
  const __half* vbp = g_v + ((size_t)(b * NKV + kv)) * SEQ * HD;
  const int row0 = qbase + wid * 16 + g;
  const int row1 = row0 + 8;

  for (int j0 = 0; j0 < jend; j0 += 64) {
    __syncthreads();
#pragma unroll
    for (int j = 0; j < 8; j++) {
      int i   = j * 128 + tid;
      int row = i >> 4;
      int seg = i & 15;
      *(uint4*)&Ks[row][seg * 8] =
          *(const uint4*)(kbp + (size_t)(j0 + row) * HD + seg * 8);
    }
#pragma unroll
    for (int j = 0; j < 8; j++) {
      int i   = j * 128 + tid;
      int row = i >> 4;
      int seg = i & 15;
      uint4 u = *(const uint4*)(vbp + (size_t)(j0 + row) * HD + seg * 8);
      const __half* hv = (const __half*)&u;
#pragma unroll
      for (int e = 0; e < 8; e++) Vs[seg * 8 + e][row] = hv[e];
    }
    __syncthreads();

    float sc[8][4];
#pragma unroll
    for (int i = 0; i < 8; i++)
#pragma unroll
      for (int j = 0; j < 4; j++) sc[i][j] = 0.f;
#pragma unroll
    for (int kt = 0; kt < 8; kt++) {
      int kb = kt * 16 + q4 * 2;
#pragma unroll
      for (int nt = 0; nt < 8; nt++) {
        uint32_t b0 = *(const uint32_t*)&Ks[nt * 8 + g][kb];
        uint32_t b1 = *(const uint32_t*)&Ks[nt * 8 + g][kb + 8];
        MMA_16816(sc[nt], qa[kt], b0, b1);
      }
    }

    if (causal && j0 == qbase) {
#pragma unroll
      for (int nt = 0; nt < 8; nt++) {
        int col = j0 + nt * 8 + q4 * 2;
        if (col     > row0) sc[nt][0] = -1e30f;
        if (col + 1 > row0) sc[nt][1] = -1e30f;
        if (col     > row1) sc[nt][2] = -1e30f;
        if (col + 1 > row1) sc[nt][3] = -1e30f;
      }
    }

    float r0 = -1e30f, r1 = -1e30f;
#pragma unroll
    for (int nt = 0; nt < 8; nt++) {
      r0 = fmaxf(r0, fmaxf(sc[nt][0], sc[nt][1]));
      r1 = fmaxf(r1, fmaxf(sc[nt][2], sc[nt][3]));
    }
    r0 = fmaxf(r0, __shfl_xor_sync(0xffffffffu, r0, 1));
    r0 = fmaxf(r0, __shfl_xor_sync(0xffffffffu, r0, 2));
    r1 = fmaxf(r1, __shfl_xor_sync(0xffffffffu, r1, 1));
    r1 = fmaxf(r1, __shfl_xor_sync(0xffffffffu, r1, 2));
    float mn0 = fmaxf(m0, r0), mn1 = fmaxf(m1, r1);
    float sf0 = __expf(m0 - mn0), sf1 = __expf(m1 - mn1);
    m0 = mn0; m1 = mn1;
    float s0 = 0.f, s1 = 0.f;
#pragma unroll
    for (int nt = 0; nt < 8; nt++) {
      sc[nt][0] = __expf(sc[nt][0] - mn0);
      sc[nt][1] = __expf(sc[nt][1] - mn0);
      sc[nt][2] = __expf(sc[nt][2] - mn1);
      sc[nt][3] = __expf(sc[nt][3] - mn1);
      s0 += sc[nt][0] + sc[nt][1];
      s1 += sc[nt][2] + sc[nt][3];
    }
    s0 += __shfl_xor_sync(0xffffffffu, s0, 1);
    s0 += __shfl_xor_sync(0xffffffffu, s0, 2);
    s1 += __shfl_xor_sync(0xffffffffu, s1, 1);
    s1 += __shfl_xor_sync(0xffffffffu, s1, 2);
    l0 = l0 * sf0 + s0;
    l1 = l1 * sf1 + s1;
#pragma unroll
    for (int i = 0; i < 16; i++) {
      o[i][0] *= sf0; o[i][1] *= sf0;
      o[i][2] *= sf1; o[i][3] *= sf1;
    }

    uint32_t pa[4][4];
#pragma unroll
    for (int kt = 0; kt < 4; kt++) {
      pa[kt][0] = pack_half2(sc[2 * kt][0], sc[2 * kt][1]);
      pa[kt][1] = pack_half2(sc[2 * kt][2], sc[2 * kt][3]);
      pa[kt][2] = pack_half2(sc[2 * kt + 1][0], sc[2 * kt + 1][1]);
      pa[kt][3] = pack_half2(sc[2 * kt + 1][2], sc[2 * kt + 1][3]);
    }

#pragma unroll
    for (int kt = 0; kt < 4; kt++) {
      int kb = kt * 16 + q4 * 2;
#pragma unroll
      for (int nt = 0; nt < 16; nt++) {
        uint32_t b0 = *(const uint32_t*)&Vs[nt * 8 + g][kb];
        uint32_t b1 = *(const uint32_t*)&Vs[nt * 8 + g][kb + 8];
        MMA_16816(o[nt], pa[kt], b0, b1);
      }
    }
  }

  float inv0 = 1.f / l0, inv1 = 1.f / l1;
#pragma unroll
  for (int nt = 0; nt < 16; nt++) {
    int d = nt * 8 + q4 * 2;
    float* p0 = &g_o[((size_t)(b * SEQ + row0)) * (NH * HD) + h * HD + d];
    float* p1 = &g_o[((size_t)(b * SEQ + row1)) * (NH * HD) + h * HD + d];
    *(float2*)p0 = make_float2(o[nt][0] * inv0, o[nt][1] * inv0);
    *(float2*)p1 = make_float2(o[nt][2] * inv1, o[nt][3] * inv1);
  }
}

// ---------------------------------------------------------------------------
// Launch
// ---------------------------------------------------------------------------
extern "C" void kernel_launch(void* const* d_in, const int* in_sizes, int n_in,
                              void* d_out, int out_size) {
  const float* x  = (const float*)d_in[0];
  const float* Wq = (const float*)d_in[1];
  const float* Wk = (const float*)d_in[2];
  const float* Wv = (const float*)d_in[3];
  const float* Wo = (const float*)d_in[4];
  const int* is_causal = (const int*)d_in[5];
  float* out = (float*)d_out;

  float* g_o_ptr = nullptr;
  cudaGetSymbolAddress((void**)&g_o_ptr, g_o);

  rope_init_kernel<<<(SEQ * 64 + 255) / 256, 256>>>();

  gemm_split_kernel<0><<<dim3((NH * HD) / 128, (BATCH * SEQ) / 128), 256>>>(
      x, Wq, nullptr, NH * HD);
  gemm_split_kernel<1><<<dim3((NKV * HD) / 128, (BATCH * SEQ) / 128), 256>>>(
      x, Wk, nullptr, NKV * HD);
  gemm_split_kernel<2><<<dim3((NKV * HD) / 128, (BATCH * SEQ) / 128), 256>>>(
      x, Wv, nullptr, NKV * HD);

  attn_kernel<<<dim3(SEQ / 64, NH, BATCH), 128>>>(is_causal);

  gemm_split_kernel<3><<<dim3(DMODEL / 128, (BATCH * SEQ) / 128), 256>>>(
      g_o_ptr, Wo, out, DMODEL);
}

// round 4
// speedup vs baseline: 2.0730x; 2.0730x over previous
#include <cuda_runtime.h>
#include <cuda_fp16.h>
#include <math.h>
#include <stdint.h>

#define BATCH  2
#define SEQ    2048
#define DMODEL 2048
#define NH     16
#define NKV    8
#define HD     128
#define KBIG   (3 * DMODEL)   // 6144: [hi | lo | hi] split-K layout
#define MROWS  (BATCH * SEQ)  // 4096

// ---------------------------------------------------------------------------
// Scratch (device globals; no allocation allowed)
// ---------------------------------------------------------------------------
__device__ __half g_xbig[(size_t)MROWS * KBIG];     // [m][6144] = [xh|xl|xh]
__device__ __half g_obig[(size_t)MROWS * KBIG];     // [m][6144] = [oh|ol|oh]
__device__ __half g_wqt [(size_t)(NH  * HD) * KBIG]; // [n][6144] = [Wh|Wh|Wl]
__device__ __half g_wkt [(size_t)(NKV * HD) * KBIG];
__device__ __half g_wvt [(size_t)(NKV * HD) * KBIG];
__device__ __half g_wot [(size_t)DMODEL * KBIG];
__device__ __half g_q[(size_t)BATCH * NH  * SEQ * HD];
__device__ __half g_k[(size_t)BATCH * NKV * SEQ * HD];
__device__ __half g_v[(size_t)BATCH * NKV * SEQ * HD];
__device__ float  g_cos[SEQ * (HD / 2)];
__device__ float  g_sin[SEQ * (HD / 2)];

// ---------------------------------------------------------------------------
// Helpers
// ---------------------------------------------------------------------------
__device__ __forceinline__ uint32_t pack_half2(float a, float b) {
  __half2 h = __floats2half2_rn(a, b);
  return *reinterpret_cast<uint32_t*>(&h);
}

#define MMA_16816(C, A, B0, B1)                                              \
  asm volatile(                                                              \
      "mma.sync.aligned.m16n8k16.row.col.f32.f16.f16.f32 "                   \
      "{%0,%1,%2,%3}, {%4,%5,%6,%7}, {%8,%9}, {%0,%1,%2,%3};\n"              \
      : "+f"((C)[0]), "+f"((C)[1]), "+f"((C)[2]), "+f"((C)[3])               \
      : "r"((A)[0]), "r"((A)[1]), "r"((A)[2]), "r"((A)[3]),                  \
        "r"(B0), "r"(B1))

#define LDSM_X4(R0, R1, R2, R3, ADDR)                                        \
  asm volatile(                                                              \
      "ldmatrix.sync.aligned.m8n8.x4.shared.b16 {%0,%1,%2,%3}, [%4];\n"      \
      : "=r"(R0), "=r"(R1), "=r"(R2), "=r"(R3) : "r"(ADDR))

#define CP_ASYNC16(DST, SRC)                                                 \
  asm volatile("cp.async.cg.shared.global [%0], [%1], 16;\n" ::              \
                   "r"(DST), "l"(SRC))
#define CP_COMMIT() asm volatile("cp.async.commit_group;\n")
#define CP_WAIT(N)  asm volatile("cp.async.wait_group %0;\n" ::"n"(N))

// ---------------------------------------------------------------------------
// Precompute kernels
// ---------------------------------------------------------------------------
__global__ void rope_init_kernel() {
  int idx = blockIdx.x * blockDim.x + threadIdx.x;
  if (idx < SEQ * (HD / 2)) {
    int s = idx >> 6;
    int i = idx & 63;
    float inv = (float)pow(10000.0, -(double)(2 * i) / (double)HD);
    float a = (float)s * inv;
    g_cos[idx] = cosf(a);
    g_sin[idx] = sinf(a);
  }
}

// x[m][k] fp32 -> g_xbig[m] = [xh | xl | xh]
__global__ void split_x_kernel(const float* __restrict__ x) {
  int idx = blockIdx.x * blockDim.x + threadIdx.x;
  if (idx < MROWS * DMODEL) {
    int m = idx >> 11;
    int k = idx & (DMODEL - 1);
    float v = x[idx];
    __half h = __float2half_rn(v);
    __half l = __float2half_rn(v - __half2float(h));
    __half* row = g_xbig + (size_t)m * KBIG;
    row[k]              = h;
    row[DMODEL + k]     = l;
    row[2 * DMODEL + k] = h;
  }
}

// W[k][n] fp32 -> Wt[n] = [Wh | Wh | Wl]  (tiled transpose)
__global__ void tsplit_w_kernel(const float* __restrict__ W,
                                __half* __restrict__ Wt, int N) {
  __shared__ float tile[32][33];
  const int n0 = blockIdx.x * 32;
  const int k0 = blockIdx.y * 32;
  const int tx = threadIdx.x;
  const int ty = threadIdx.y;  // 0..7
#pragma unroll
  for (int j = 0; j < 32; j += 8)
    tile[ty + j][tx] = W[(size_t)(k0 + ty + j) * N + n0 + tx];
  __syncthreads();
#pragma unroll
  for (int j = 0; j < 32; j += 8) {
    int n = n0 + ty + j;
    int k = k0 + tx;
    float v = tile[tx][ty + j];
    __half h = __float2half_rn(v);
    __half l = __float2half_rn(v - __half2float(h));
    __half* row = Wt + (size_t)n * KBIG;
    row[k]              = h;
    row[DMODEL + k]     = h;
    row[2 * DMODEL + k] = l;
  }
}

// ---------------------------------------------------------------------------
// Pipelined fp16 GEMM: C[4096, N] = A[4096, KBIG] @ Bt[N, KBIG]^T
// Block 128x128, BK=64, 3-stage cp.async, 256 threads = 8 warps (4M x 2N),
// warp tile 32x64, ldmatrix.x4 fragments, pad-72 smem rows.
// MODE 0: Q (rope + 1/sqrt(hd) -> g_q)  MODE 1: K (rope -> g_k)
// MODE 2: V (-> g_v)                    MODE 3: out proj (-> out fp32)
// ---------------------------------------------------------------------------
#define BK      64
#define STRIDE  72                      // halves per smem row
#define STAGE_H (128 * STRIDE)          // halves per stage per array
#define NITERS  (KBIG / BK)             // 96

template <int MODE>
__global__ __launch_bounds__(256) void gemm_f16_kernel(
    const __half* __restrict__ A, const __half* __restrict__ Bt,
    float* __restrict__ out, int N) {
  extern __shared__ __align__(16) __half smem[];
  __half* As = smem;                    // [3][128][72]
  __half* Bs = smem + 3 * STAGE_H;      // [3][128][72]

  const int tid  = threadIdx.x;
  const int wid  = tid >> 5;
  const int lane = tid & 31;
  const int wm   = wid >> 1;
  const int wn   = wid & 1;
  const int g    = lane >> 2;
  const int q4   = lane & 3;
  const int m0   = blockIdx.y * 128;
  const int n0   = blockIdx.x * 128;

  const uint32_t as_base = (uint32_t)__cvta_generic_to_shared(As);
  const uint32_t bs_base = (uint32_t)__cvta_generic_to_shared(Bs);

  // cp.async per-thread chunk: 1024 chunks of 16B per array per stage
  const int crow = tid >> 3;            // 0..31 (x4 in j loop -> 128 rows)
  const int cseg = tid & 7;             // 16B segment within 128B row

  // ldmatrix fragment offsets (bytes, within a stage)
  const uint32_t a_off =
      (uint32_t)((wm * 32 + (lane & 15)) * STRIDE + (lane >> 4) * 8) * 2;
  const uint32_t b_off =
      (uint32_t)((wn * 64 + (lane & 7) + ((lane & 16) >> 1)) * STRIDE +
                 (lane & 8)) * 2;

  float c[2][8][4];
#pragma unroll
  for (int mt = 0; mt < 2; mt++)
#pragma unroll
    for (int nt = 0; nt < 8; nt++)
#pragma unroll
      for (int j = 0; j < 4; j++) c[mt][nt][j] = 0.f;

  auto load_stage = [&](int stg, int k0) {
    uint32_t abase = as_base + stg * STAGE_H * 2;
    uint32_t bbase = bs_base + stg * STAGE_H * 2;
#pragma unroll
    for (int j = 0; j < 4; j++) {
      int row = j * 32 + crow;
      uint32_t so = (uint32_t)(row * STRIDE + cseg * 8) * 2;
      CP_ASYNC16(abase + so, A + (size_t)(m0 + row) * KBIG + k0 + cseg * 8);
      CP_ASYNC16(bbase + so, Bt + (size_t)(n0 + row) * KBIG + k0 + cseg * 8);
    }
  };

  load_stage(0, 0);
  CP_COMMIT();
  load_stage(1, BK);
  CP_COMMIT();

  for (int it = 0; it < NITERS; it++) {
    CP_WAIT(1);
    __syncthreads();
    if (it + 2 < NITERS) load_stage((it + 2) % 3, (it + 2) * BK);
    CP_COMMIT();

    const int stg = it % 3;
    const uint32_t ab = as_base + stg * STAGE_H * 2 + a_off;
    const uint32_t bb = bs_base + stg * STAGE_H * 2 + b_off;
#pragma unroll
    for (int kt = 0; kt < 4; kt++) {
      const uint32_t ko = kt * 32;  // 16 halves
      uint32_t a[2][4];
      LDSM_X4(a[0][0], a[0][1], a[0][2], a[0][3], ab + ko);
      LDSM_X4(a[1][0], a[1][1], a[1][2], a[1][3], ab + 16 * STRIDE * 2 + ko);
#pragma unroll
      for (int p = 0; p < 4; p++) {
        uint32_t b[4];
        LDSM_X4(b[0], b[1], b[2], b[3], bb + p * 16 * STRIDE * 2 + ko);
#pragma unroll
        for (int mt = 0; mt < 2; mt++) {
          MMA_16816(c[mt][2 * p],     a[mt], b[0], b[1]);
          MMA_16816(c[mt][2 * p + 1], a[mt], b[2], b[3]);
        }
      }
    }
    __syncthreads();
  }

  // Epilogue
  const float qscale = 0.08838834764831845f;  // 1/sqrt(128)
#pragma unroll
  for (int mt = 0; mt < 2; mt++) {
#pragma unroll
    for (int nt = 0; nt < 8; nt++) {
      int col = n0 + wn * 64 + nt * 8 + q4 * 2;
      int row = m0 + wm * 32 + mt * 16 + g;
      if (MODE == 3) {
        *(float2*)&out[(size_t)row * DMODEL + col] =
            make_float2(c[mt][nt][0], c[mt][nt][1]);
        *(float2*)&out[(size_t)(row + 8) * DMODEL + col] =
            make_float2(c[mt][nt][2], c[mt][nt][3]);
      } else {
        int head = col >> 7;
        int d    = col & 127;
#pragma unroll
        for (int hh = 0; hh < 2; hh++) {
          int r = row + hh * 8;
          int b = r >> 11;
          int s = r & 2047;
          float v0 = c[mt][nt][hh * 2];
          float v1 = c[mt][nt][hh * 2 + 1];
          if (MODE != 2) {
            int i    = d >> 1;
            float cs = g_cos[s * 64 + i];
            float sn = g_sin[s * 64 + i];
            float r0 = v0 * cs - v1 * sn;
            float r1 = v0 * sn + v1 * cs;
            v0 = r0; v1 = r1;
            if (MODE == 0) { v0 *= qscale; v1 *= qscale; }
          }
          __half* dst;
          if (MODE == 0)
            dst = &g_q[(((size_t)(b * NH + head)) * SEQ + s) * HD + d];
          else if (MODE == 1)
            dst = &g_k[(((size_t)(b * NKV + head)) * SEQ + s) * HD + d];
          else
            dst = &g_v[(((size_t)(b * NKV + head)) * SEQ + s) * HD + d];
          *(__half2*)dst = __floats2half2_rn(v0, v1);
        }
      }
    }
  }
}

// ---------------------------------------------------------------------------
// Flash attention (round-2 proven version); epilogue writes split g_obig.
// ---------------------------------------------------------------------------
__global__ __launch_bounds__(128) void attn_kernel(const int* __restrict__ causal_flag) {
  __shared__ __align__(16) __half Ks[64][136];
  __shared__ __align__(16) __half Vs[128][66];

  const int tid  = threadIdx.x;
  const int wid  = tid >> 5;
  const int lane = tid & 31;
  const int g    = lane >> 2;
  const int q4   = lane & 3;
  const int qtile = blockIdx.x;
  const int h     = blockIdx.y;
  const int b     = blockIdx.z;
  const int kv    = h >> 1;
  const int qbase = qtile * 64;
  const int causal = *causal_flag;

  const __half* qp = g_q + (((size_t)(b * NH + h)) * SEQ + qbase) * HD;
#pragma unroll
  for (int j = 0; j < 8; j++) {
    int i   = j * 128 + tid;
    int row = i >> 4;
    int seg = i & 15;
    *(uint4*)&Ks[row][seg * 8] = *(const uint4*)(qp + row * HD + seg * 8);
  }
  __syncthreads();
  uint32_t qa[8][4];
#pragma unroll
  for (int kt = 0; kt < 8; kt++) {
    int kb = kt * 16 + q4 * 2;
    qa[kt][0] = *(const uint32_t*)&Ks[wid * 16 + g][kb];
    qa[kt][1] = *(const uint32_t*)&Ks[wid * 16 + g + 8][kb];
    qa[kt][2] = *(const uint32_t*)&Ks[wid * 16 + g][kb + 8];
    qa[kt][3] = *(const uint32_t*)&Ks[wid * 16 + g + 8][kb + 8];
  }

  float o[16][4];
#pragma unroll
  for (int i = 0; i < 16; i++)
#pragma unroll
    for (int j = 0; j < 4; j++) o[i][j] = 0.f;
  float m0 = -1e30f, m1 = -1e30f, l0 = 0.f, l1 = 0.f;

  const int jend = causal ? (qbase + 64) : SEQ;
  const __half* kbp = g_k + ((size_t)(b * NKV + kv)) * SEQ * HD;
  const __half* vbp = g_v + ((size_t)(b * NKV + kv)) * SEQ * HD;
  const int row0 = qbase + wid * 16 + g;
  const int row1 = row0 + 8;

  for (int j0 = 0; j0 < jend; j0 += 64) {
    __syncthreads();
#pragma unroll
    for (int j = 0; j < 8; j++) {
      int i   = j * 128 + tid;
      int row = i >> 4;
      int seg = i & 15;
      *(uint4*)&Ks[row][seg * 8] =
          *(const uint4*)(kbp + (size_t)(j0 + row) * HD + seg * 8);
    }
#pragma unroll
    for (int j = 0; j < 8; j++) {
      int i   = j * 128 + tid;
      int row = i >> 4;
      int seg = i & 15;
      uint4 u = *(const uint4*)(vbp + (size_t)(j0 + row) * HD + seg * 8);
      const __half* hv = (const __half*)&u;
#pragma unroll
      for (int e = 0; e < 8; e++) Vs[seg * 8 + e][row] = hv[e];
    }
    __syncthreads();

    float sc[8][4];
#pragma unroll
    for (int i = 0; i < 8; i++)
#pragma unroll
      for (int j = 0; j < 4; j++) sc[i][j] = 0.f;
#pragma unroll
    for (int kt = 0; kt < 8; kt++) {
      int kb = kt * 16 + q4 * 2;
#pragma unroll
      for (int nt = 0; nt < 8; nt++) {
        uint32_t b0 = *(const uint32_t*)&Ks[nt * 8 + g][kb];
        uint32_t b1 = *(const uint32_t*)&Ks[nt * 8 + g][kb + 8];
        MMA_16816(sc[nt], qa[kt], b0, b1);
      }
    }

    if (causal && j0 == qbase) {
#pragma unroll
      for (int nt = 0; nt < 8; nt++) {
        int col = j0 + nt * 8 + q4 * 2;
        if (col     > row0) sc[nt][0] = -1e30f;
        if (col + 1 > row0) sc[nt][1] = -1e30f;
        if (col     > row1) sc[nt][2] = -1e30f;
        if (col + 1 > row1) sc[nt][3] = -1e30f;
      }
    }

    float r0 = -1e30f, r1 = -1e30f;
#pragma unroll
    for (int nt = 0; nt < 8; nt++) {
      r0 = fmaxf(r0, fmaxf(sc[nt][0], sc[nt][1]));
      r1 = fmaxf(r1, fmaxf(sc[nt][2], sc[nt][3]));
    }
    r0 = fmaxf(r0, __shfl_xor_sync(0xffffffffu, r0, 1));
    r0 = fmaxf(r0, __shfl_xor_sync(0xffffffffu, r0, 2));
    r1 = fmaxf(r1, __shfl_xor_sync(0xffffffffu, r1, 1));
    r1 = fmaxf(r1, __shfl_xor_sync(0xffffffffu, r1, 2));
    float mn0 = fmaxf(m0, r0), mn1 = fmaxf(m1, r1);
    float sf0 = __expf(m0 - mn0), sf1 = __expf(m1 - mn1);
    m0 = mn0; m1 = mn1;
    float s0 = 0.f, s1 = 0.f;
#pragma unroll
    for (int nt = 0; nt < 8; nt++) {
      sc[nt][0] = __expf(sc[nt][0] - mn0);
      sc[nt][1] = __expf(sc[nt][1] - mn0);
      sc[nt][2] = __expf(sc[nt][2] - mn1);
      sc[nt][3] = __expf(sc[nt][3] - mn1);
      s0 += sc[nt][0] + sc[nt][1];
      s1 += sc[nt][2] + sc[nt][3];
    }
    s0 += __shfl_xor_sync(0xffffffffu, s0, 1);
    s0 += __shfl_xor_sync(0xffffffffu, s0, 2);
    s1 += __shfl_xor_sync(0xffffffffu, s1, 1);
    s1 += __shfl_xor_sync(0xffffffffu, s1, 2);
    l0 = l0 * sf0 + s0;
    l1 = l1 * sf1 + s1;
#pragma unroll
    for (int i = 0; i < 16; i++) {
      o[i][0] *= sf0; o[i][1] *= sf0;
      o[i][2] *= sf1; o[i][3] *= sf1;
    }

    uint32_t pa[4][4];
#pragma unroll
    for (int kt = 0; kt < 4; kt++) {
      pa[kt][0] = pack_half2(sc[2 * kt][0], sc[2 * kt][1]);
      pa[kt][1] = pack_half2(sc[2 * kt][2], sc[2 * kt][3]);
      pa[kt][2] = pack_half2(sc[2 * kt + 1][0], sc[2 * kt + 1][1]);
      pa[kt][3] = pack_half2(sc[2 * kt + 1][2], sc[2 * kt + 1][3]);
    }

#pragma unroll
    for (int kt = 0; kt < 4; kt++) {
      int kb = kt * 16 + q4 * 2;
#pragma unroll
      for (int nt = 0; nt < 16; nt++) {
        uint32_t b0 = *(const uint32_t*)&Vs[nt * 8 + g][kb];
        uint32_t b1 = *(const uint32_t*)&Vs[nt * 8 + g][kb + 8];
        MMA_16816(o[nt], pa[kt], b0, b1);
      }
    }
  }

  // Normalize, split to hi/lo, store into g_obig = [oh | ol | oh]
  float inv0 = 1.f / l0, inv1 = 1.f / l1;
#pragma unroll
  for (int nt = 0; nt < 16; nt++) {
    int d = nt * 8 + q4 * 2;
#pragma unroll
    for (int hh = 0; hh < 2; hh++) {
      int r = (hh == 0) ? row0 : row1;
      float v0 = o[nt][hh * 2]     * (hh == 0 ? inv0 : inv1);
      float v1 = o[nt][hh * 2 + 1] * (hh == 0 ? inv0 : inv1);
      __half h0 = __float2half_rn(v0);
      __half h1 = __float2half_rn(v1);
      __half e0 = __float2half_rn(v0 - __half2float(h0));
      __half e1 = __float2half_rn(v1 - __half2float(h1));
      __half* base = g_obig + (size_t)(b * SEQ + r) * KBIG + h * HD + d;
      *(__half2*)(base)              = __halves2half2(h0, h1);
      *(__half2*)(base + DMODEL)     = __halves2half2(e0, e1);
      *(__half2*)(base + 2 * DMODEL) = __halves2half2(h0, h1);
    }
  }
}

// ---------------------------------------------------------------------------
// Launch
// ---------------------------------------------------------------------------
extern "C" void kernel_launch(void* const* d_in, const int* in_sizes, int n_in,
                              void* d_out, int out_size) {
  const float* x  = (const float*)d_in[0];
  const float* Wq = (const float*)d_in[1];
  const float* Wk = (const float*)d_in[2];
  const float* Wv = (const float*)d_in[3];
  const float* Wo = (const float*)d_in[4];
  const int* is_causal = (const int*)d_in[5];
  float* out = (float*)d_out;

  __half *xbig, *obig, *wqt, *wkt, *wvt, *wot;
  cudaGetSymbolAddress((void**)&xbig, g_xbig);
  cudaGetSymbolAddress((void**)&obig, g_obig);
  cudaGetSymbolAddress((void**)&wqt, g_wqt);
  cudaGetSymbolAddress((void**)&wkt, g_wkt);
  cudaGetSymbolAddress((void**)&wvt, g_wvt);
  cudaGetSymbolAddress((void**)&wot, g_wot);

  const int smem_bytes = 6 * STAGE_H * 2;  // 110592
  cudaFuncSetAttribute(gemm_f16_kernel<0>,
                       cudaFuncAttributeMaxDynamicSharedMemorySize, smem_bytes);
  cudaFuncSetAttribute(gemm_f16_kernel<1>,
                       cudaFuncAttributeMaxDynamicSharedMemorySize, smem_bytes);
  cudaFuncSetAttribute(gemm_f16_kernel<2>,
                       cudaFuncAttributeMaxDynamicSharedMemorySize, smem_bytes);
  cudaFuncSetAttribute(gemm_f16_kernel<3>,
                       cudaFuncAttributeMaxDynamicSharedMemorySize, smem_bytes);

  rope_init_kernel<<<(SEQ * 64 + 255) / 256, 256>>>();
  split_x_kernel<<<(MROWS * DMODEL) / 256, 256>>>(x);
  tsplit_w_kernel<<<dim3((NH  * HD) / 32, DMODEL / 32), dim3(32, 8)>>>(Wq, wqt, NH * HD);
  tsplit_w_kernel<<<dim3((NKV * HD) / 32, DMODEL / 32), dim3(32, 8)>>>(Wk, wkt, NKV * HD);
  tsplit_w_kernel<<<dim3((NKV * HD) / 32, DMODEL / 32), dim3(32, 8)>>>(Wv, wvt, NKV * HD);
  tsplit_w_kernel<<<dim3(DMODEL / 32, DMODEL / 32), dim3(32, 8)>>>(Wo, wot, DMODEL);

  gemm_f16_kernel<0><<<dim3((NH * HD) / 128, MROWS / 128), 256, smem_bytes>>>(
      xbig, wqt, nullptr, NH * HD);
  gemm_f16_kernel<1><<<dim3((NKV * HD) / 128, MROWS / 128), 256, smem_bytes>>>(
      xbig, wkt, nullptr, NKV * HD);
  gemm_f16_kernel<2><<<dim3((NKV * HD) / 128, MROWS / 128), 256, smem_bytes>>>(
      xbig, wvt, nullptr, NKV * HD);

  attn_kernel<<<dim3(SEQ / 64, NH, BATCH), 128>>>(is_causal);

  gemm_f16_kernel<3><<<dim3(DMODEL / 128, MROWS / 128), 256, smem_bytes>>>(
      obig, wot, out, DMODEL);
}

// round 5
// speedup vs baseline: 2.5473x; 1.2288x over previous
#include <cuda_runtime.h>
#include <cuda_fp16.h>
#include <math.h>
#include <stdint.h>

#define BATCH  2
#define SEQ    2048
#define DMODEL 2048
#define NH     16
#define NKV    8
#define HD     128
#define KBIG   (3 * DMODEL)   // 6144: [hi | lo | hi] split-K layout
#define MROWS  (BATCH * SEQ)  // 4096
#define NQKV   (NH * HD + 2 * NKV * HD)  // 4096 combined QKV columns

// ---------------------------------------------------------------------------
// Scratch (device globals; no allocation allowed)
// ---------------------------------------------------------------------------
__device__ __half g_xbig[(size_t)MROWS * KBIG];       // [m][6144] = [xh|xl|xh]
__device__ __half g_obig[(size_t)MROWS * KBIG];       // [m][6144] = [oh|ol|oh]
__device__ __half g_wt  [(size_t)NQKV * KBIG];        // [n][6144] = [Wh|Wh|Wl] (Q|K|V)
__device__ __half g_wot [(size_t)DMODEL * KBIG];
__device__ __half g_q[(size_t)BATCH * NH  * SEQ * HD];
__device__ __half g_k[(size_t)BATCH * NKV * SEQ * HD];
__device__ __half g_v[(size_t)BATCH * NKV * SEQ * HD];
__device__ float  g_cos[SEQ * (HD / 2)];
__device__ float  g_sin[SEQ * (HD / 2)];

// ---------------------------------------------------------------------------
// Helpers
// ---------------------------------------------------------------------------
__device__ __forceinline__ uint32_t pack_half2(float a, float b) {
  __half2 h = __floats2half2_rn(a, b);
  return *reinterpret_cast<uint32_t*>(&h);
}

#define MMA_16816(C, A, B0, B1)                                              \
  asm volatile(                                                              \
      "mma.sync.aligned.m16n8k16.row.col.f32.f16.f16.f32 "                   \
      "{%0,%1,%2,%3}, {%4,%5,%6,%7}, {%8,%9}, {%0,%1,%2,%3};\n"              \
      : "+f"((C)[0]), "+f"((C)[1]), "+f"((C)[2]), "+f"((C)[3])               \
      : "r"((A)[0]), "r"((A)[1]), "r"((A)[2]), "r"((A)[3]),                  \
        "r"(B0), "r"(B1))

#define LDSM_X4(R0, R1, R2, R3, ADDR)                                        \
  asm volatile(                                                              \
      "ldmatrix.sync.aligned.m8n8.x4.shared.b16 {%0,%1,%2,%3}, [%4];\n"      \
      : "=r"(R0), "=r"(R1), "=r"(R2), "=r"(R3) : "r"(ADDR))

#define LDSM_X4_T(R0, R1, R2, R3, ADDR)                                      \
  asm volatile(                                                              \
      "ldmatrix.sync.aligned.m8n8.x4.trans.shared.b16 {%0,%1,%2,%3}, [%4];\n"\
      : "=r"(R0), "=r"(R1), "=r"(R2), "=r"(R3) : "r"(ADDR))

#define CP_ASYNC16(DST, SRC)                                                 \
  asm volatile("cp.async.cg.shared.global [%0], [%1], 16;\n" ::              \
                   "r"(DST), "l"(SRC))
#define CP_COMMIT() asm volatile("cp.async.commit_group;\n")
#define CP_WAIT(N)  asm volatile("cp.async.wait_group %0;\n" ::"n"(N))

// ---------------------------------------------------------------------------
// Precompute kernels
// ---------------------------------------------------------------------------
__global__ void rope_init_kernel() {
  int idx = blockIdx.x * blockDim.x + threadIdx.x;
  if (idx < SEQ * (HD / 2)) {
    int s = idx >> 6;
    int i = idx & 63;
    float inv = (float)pow(10000.0, -(double)(2 * i) / (double)HD);
    float a = (float)s * inv;
    g_cos[idx] = cosf(a);
    g_sin[idx] = sinf(a);
  }
}

__global__ void split_x_kernel(const float* __restrict__ x) {
  int idx = blockIdx.x * blockDim.x + threadIdx.x;
  if (idx < MROWS * DMODEL) {
    int m = idx >> 11;
    int k = idx & (DMODEL - 1);
    float v = x[idx];
    __half h = __float2half_rn(v);
    __half l = __float2half_rn(v - __half2float(h));
    __half* row = g_xbig + (size_t)m * KBIG;
    row[k]              = h;
    row[DMODEL + k]     = l;
    row[2 * DMODEL + k] = h;
  }
}

// W[k][n] fp32 -> Wt[n] = [Wh | Wh | Wl]  (tiled transpose)
__global__ void tsplit_w_kernel(const float* __restrict__ W,
                                __half* __restrict__ Wt, int N) {
  __shared__ float tile[32][33];
  const int n0 = blockIdx.x * 32;
  const int k0 = blockIdx.y * 32;
  const int tx = threadIdx.x;
  const int ty = threadIdx.y;
#pragma unroll
  for (int j = 0; j < 32; j += 8)
    tile[ty + j][tx] = W[(size_t)(k0 + ty + j) * N + n0 + tx];
  __syncthreads();
#pragma unroll
  for (int j = 0; j < 32; j += 8) {
    int n = n0 + ty + j;
    int k = k0 + tx;
    float v = tile[tx][ty + j];
    __half h = __float2half_rn(v);
    __half l = __float2half_rn(v - __half2float(h));
    __half* row = Wt + (size_t)n * KBIG;
    row[k]              = h;
    row[DMODEL + k]     = h;
    row[2 * DMODEL + k] = l;
  }
}

// ---------------------------------------------------------------------------
// Pipelined fp16 GEMM: C[4096, N] = A[4096, KBIG] @ Bt[N, KBIG]^T
// Block 128x128, BK=64, 3-stage cp.async (single sync/iter), 256 threads,
// 8 warps (4M x 2N), warp tile 32x64, ldmatrix.x4, pad-72 smem rows.
// MODE 0: merged QKV epilogue (rope etc.)   MODE 3: out proj (fp32)
// ---------------------------------------------------------------------------
#define BK      64
#define STRIDE  72
#define STAGE_H (128 * STRIDE)
#define NITERS  (KBIG / BK)   // 96

template <int MODE>
__global__ __launch_bounds__(256) void gemm_f16_kernel(
    const __half* __restrict__ A, const __half* __restrict__ Bt,
    float* __restrict__ out) {
  extern __shared__ __align__(16) __half smem[];
  __half* As = smem;
  __half* Bs = smem + 3 * STAGE_H;

  const int tid  = threadIdx.x;
  const int wid  = tid >> 5;
  const int lane = tid & 31;
  const int wm   = wid >> 1;
  const int wn   = wid & 1;
  const int g    = lane >> 2;
  const int q4   = lane & 3;
  const int m0   = blockIdx.y * 128;
  const int n0   = blockIdx.x * 128;

  const uint32_t as_base = (uint32_t)__cvta_generic_to_shared(As);
  const uint32_t bs_base = (uint32_t)__cvta_generic_to_shared(Bs);

  const int crow = tid >> 3;
  const int cseg = tid & 7;

  const uint32_t a_off =
      (uint32_t)((wm * 32 + (lane & 15)) * STRIDE + (lane >> 4) * 8) * 2;
  const uint32_t b_off =
      (uint32_t)((wn * 64 + (lane & 7) + ((lane & 16) >> 1)) * STRIDE +
                 (lane & 8)) * 2;

  float c[2][8][4];
#pragma unroll
  for (int mt = 0; mt < 2; mt++)
#pragma unroll
    for (int nt = 0; nt < 8; nt++)
#pragma unroll
      for (int j = 0; j < 4; j++) c[mt][nt][j] = 0.f;

  auto load_stage = [&](int stg, int k0) {
    uint32_t abase = as_base + stg * STAGE_H * 2;
    uint32_t bbase = bs_base + stg * STAGE_H * 2;
#pragma unroll
    for (int j = 0; j < 4; j++) {
      int row = j * 32 + crow;
      uint32_t so = (uint32_t)(row * STRIDE + cseg * 8) * 2;
      CP_ASYNC16(abase + so, A + (size_t)(m0 + row) * KBIG + k0 + cseg * 8);
      CP_ASYNC16(bbase + so, Bt + (size_t)(n0 + row) * KBIG + k0 + cseg * 8);
    }
  };

  load_stage(0, 0);
  CP_COMMIT();
  load_stage(1, BK);
  CP_COMMIT();

  for (int it = 0; it < NITERS; it++) {
    CP_WAIT(1);
    __syncthreads();
    if (it + 2 < NITERS) load_stage((it + 2) % 3, (it + 2) * BK);
    CP_COMMIT();

    const int stg = it % 3;
    const uint32_t ab = as_base + stg * STAGE_H * 2 + a_off;
    const uint32_t bb = bs_base + stg * STAGE_H * 2 + b_off;
#pragma unroll
    for (int kt = 0; kt < 4; kt++) {
      const uint32_t ko = kt * 32;
      uint32_t a[2][4];
      LDSM_X4(a[0][0], a[0][1], a[0][2], a[0][3], ab + ko);
      LDSM_X4(a[1][0], a[1][1], a[1][2], a[1][3], ab + 16 * STRIDE * 2 + ko);
#pragma unroll
      for (int p = 0; p < 4; p++) {
        uint32_t b[4];
        LDSM_X4(b[0], b[1], b[2], b[3], bb + p * 16 * STRIDE * 2 + ko);
#pragma unroll
        for (int mt = 0; mt < 2; mt++) {
          MMA_16816(c[mt][2 * p],     a[mt], b[0], b[1]);
          MMA_16816(c[mt][2 * p + 1], a[mt], b[2], b[3]);
        }
      }
    }
  }
  // No trailing sync needed: epilogue touches no shared memory.

  const float qscale = 0.08838834764831845f;  // 1/sqrt(128)
#pragma unroll
  for (int mt = 0; mt < 2; mt++) {
#pragma unroll
    for (int nt = 0; nt < 8; nt++) {
      int col = n0 + wn * 64 + nt * 8 + q4 * 2;
      int row = m0 + wm * 32 + mt * 16 + g;
      if (MODE == 3) {
        *(float2*)&out[(size_t)row * DMODEL + col] =
            make_float2(c[mt][nt][0], c[mt][nt][1]);
        *(float2*)&out[(size_t)(row + 8) * DMODEL + col] =
            make_float2(c[mt][nt][2], c[mt][nt][3]);
      } else {
#pragma unroll
        for (int hh = 0; hh < 2; hh++) {
          int r = row + hh * 8;
          int b = r >> 11;
          int s = r & 2047;
          float v0 = c[mt][nt][hh * 2];
          float v1 = c[mt][nt][hh * 2 + 1];
          __half* dst;
          if (col < NH * HD) {            // Q: rope + scale
            int head = col >> 7, d = col & 127;
            int i    = d >> 1;
            float cs = g_cos[s * 64 + i], sn = g_sin[s * 64 + i];
            float r0 = v0 * cs - v1 * sn, r1 = v0 * sn + v1 * cs;
            v0 = r0 * qscale; v1 = r1 * qscale;
            dst = &g_q[(((size_t)(b * NH + head)) * SEQ + s) * HD + d];
          } else if (col < NH * HD + NKV * HD) {  // K: rope
            int kc = col - NH * HD;
            int head = kc >> 7, d = kc & 127;
            int i    = d >> 1;
            float cs = g_cos[s * 64 + i], sn = g_sin[s * 64 + i];
            float r0 = v0 * cs - v1 * sn, r1 = v0 * sn + v1 * cs;
            v0 = r0; v1 = r1;
            dst = &g_k[(((size_t)(b * NKV + head)) * SEQ + s) * HD + d];
          } else {                        // V
            int vc = col - NH * HD - NKV * HD;
            int head = vc >> 7, d = vc & 127;
            dst = &g_v[(((size_t)(b * NKV + head)) * SEQ + s) * HD + d];
          }
          *(__half2*)dst = __floats2half2_rn(v0, v1);
        }
      }
    }
  }
}

// ---------------------------------------------------------------------------
// Flash attention v2: block = (qtile of 128 rows, head, batch), 256 threads
// (8 warps x 16 rows). KV chunks of 64, natural [s][d] smem, all fragments
// via ldmatrix (V via ldmatrix.trans — no smem transpose).
// ---------------------------------------------------------------------------
#define AS_ROW 136   // halves per smem row

__global__ __launch_bounds__(256) void attn_kernel(const int* __restrict__ causal_flag) {
  __shared__ __align__(16) __half S[128 * AS_ROW];  // K rows 0-63, V rows 64-127

  const int tid  = threadIdx.x;
  const int wid  = tid >> 5;
  const int lane = tid & 31;
  const int g    = lane >> 2;
  const int q4   = lane & 3;
  const int qtile = blockIdx.x;
  const int h     = blockIdx.y;
  const int b     = blockIdx.z;
  const int kv    = h >> 1;
  const int qbase = qtile * 128;
  const int causal = *causal_flag;

  const uint32_t s_base = (uint32_t)__cvta_generic_to_shared(S);
  const uint32_t q_a = s_base +
      (uint32_t)((wid * 16 + (lane & 15)) * AS_ROW + (lane >> 4) * 8) * 2;
  const uint32_t k_b = s_base +
      (uint32_t)(((lane & 7) + ((lane & 16) >> 1)) * AS_ROW + (lane & 8)) * 2;
  const uint32_t v_b = s_base +
      (uint32_t)((64 + (lane & 15)) * AS_ROW + (lane >> 4) * 8) * 2;

  // Stage Q tile (128 x 128) and extract A fragments
  const __half* qp = g_q + (((size_t)(b * NH + h)) * SEQ + qbase) * HD;
#pragma unroll
  for (int j = 0; j < 8; j++) {
    int i   = j * 256 + tid;
    int row = i >> 4;
    int seg = i & 15;
    *(uint4*)&S[row * AS_ROW + seg * 8] = *(const uint4*)(qp + row * HD + seg * 8);
  }
  __syncthreads();
  uint32_t qa[8][4];
#pragma unroll
  for (int kt = 0; kt < 8; kt++)
    LDSM_X4(qa[kt][0], qa[kt][1], qa[kt][2], qa[kt][3], q_a + kt * 32);

  float o[16][4];
#pragma unroll
  for (int i = 0; i < 16; i++)
#pragma unroll
    for (int j = 0; j < 4; j++) o[i][j] = 0.f;
  float m0 = -1e30f, m1 = -1e30f, l0 = 0.f, l1 = 0.f;

  const int jend = causal ? (qbase + 128) : SEQ;
  const __half* kbp = g_k + ((size_t)(b * NKV + kv)) * SEQ * HD;
  const __half* vbp = g_v + ((size_t)(b * NKV + kv)) * SEQ * HD;
  const int row0 = qbase + wid * 16 + g;
  const int row1 = row0 + 8;

  for (int j0 = 0; j0 < jend; j0 += 64) {
    __syncthreads();  // previous chunk reads / Q frag extraction complete
#pragma unroll
    for (int j = 0; j < 4; j++) {
      int i   = j * 256 + tid;
      int row = i >> 4;
      int seg = i & 15;
      *(uint4*)&S[row * AS_ROW + seg * 8] =
          *(const uint4*)(kbp + (size_t)(j0 + row) * HD + seg * 8);
      *(uint4*)&S[(64 + row) * AS_ROW + seg * 8] =
          *(const uint4*)(vbp + (size_t)(j0 + row) * HD + seg * 8);
    }
    __syncthreads();

    // S = Q @ K^T : per warp 16 x 64
    float sc[8][4];
#pragma unroll
    for (int i = 0; i < 8; i++)
#pragma unroll
      for (int j = 0; j < 4; j++) sc[i][j] = 0.f;
#pragma unroll
    for (int kt = 0; kt < 8; kt++) {
#pragma unroll
      for (int p = 0; p < 4; p++) {
        uint32_t bf[4];
        LDSM_X4(bf[0], bf[1], bf[2], bf[3],
                k_b + (uint32_t)(p * 16 * AS_ROW * 2) + kt * 32);
        MMA_16816(sc[2 * p],     qa[kt], bf[0], bf[1]);
        MMA_16816(sc[2 * p + 1], qa[kt], bf[2], bf[3]);
      }
    }

    if (causal && j0 + 64 > qbase) {
#pragma unroll
      for (int nt = 0; nt < 8; nt++) {
        int col = j0 + nt * 8 + q4 * 2;
        if (col     > row0) sc[nt][0] = -1e30f;
        if (col + 1 > row0) sc[nt][1] = -1e30f;
        if (col     > row1) sc[nt][2] = -1e30f;
        if (col + 1 > row1) sc[nt][3] = -1e30f;
      }
    }

    float r0 = -1e30f, r1 = -1e30f;
#pragma unroll
    for (int nt = 0; nt < 8; nt++) {
      r0 = fmaxf(r0, fmaxf(sc[nt][0], sc[nt][1]));
      r1 = fmaxf(r1, fmaxf(sc[nt][2], sc[nt][3]));
    }
    r0 = fmaxf(r0, __shfl_xor_sync(0xffffffffu, r0, 1));
    r0 = fmaxf(r0, __shfl_xor_sync(0xffffffffu, r0, 2));
    r1 = fmaxf(r1, __shfl_xor_sync(0xffffffffu, r1, 1));
    r1 = fmaxf(r1, __shfl_xor_sync(0xffffffffu, r1, 2));
    float mn0 = fmaxf(m0, r0), mn1 = fmaxf(m1, r1);
    float sf0 = __expf(m0 - mn0), sf1 = __expf(m1 - mn1);
    m0 = mn0; m1 = mn1;
    float s0 = 0.f, s1 = 0.f;
#pragma unroll
    for (int nt = 0; nt < 8; nt++) {
      sc[nt][0] = __expf(sc[nt][0] - mn0);
      sc[nt][1] = __expf(sc[nt][1] - mn0);
      sc[nt][2] = __expf(sc[nt][2] - mn1);
      sc[nt][3] = __expf(sc[nt][3] - mn1);
      s0 += sc[nt][0] + sc[nt][1];
      s1 += sc[nt][2] + sc[nt][3];
    }
    s0 += __shfl_xor_sync(0xffffffffu, s0, 1);
    s0 += __shfl_xor_sync(0xffffffffu, s0, 2);
    s1 += __shfl_xor_sync(0xffffffffu, s1, 1);
    s1 += __shfl_xor_sync(0xffffffffu, s1, 2);
    l0 = l0 * sf0 + s0;
    l1 = l1 * sf1 + s1;
#pragma unroll
    for (int i = 0; i < 16; i++) {
      o[i][0] *= sf0; o[i][1] *= sf0;
      o[i][2] *= sf1; o[i][3] *= sf1;
    }

    uint32_t pa[4][4];
#pragma unroll
    for (int kt = 0; kt < 4; kt++) {
      pa[kt][0] = pack_half2(sc[2 * kt][0], sc[2 * kt][1]);
      pa[kt][1] = pack_half2(sc[2 * kt][2], sc[2 * kt][3]);
      pa[kt][2] = pack_half2(sc[2 * kt + 1][0], sc[2 * kt + 1][1]);
      pa[kt][3] = pack_half2(sc[2 * kt + 1][2], sc[2 * kt + 1][3]);
    }

    // O += P @ V : V B-fragments via ldmatrix.trans from natural [s][d]
#pragma unroll
    for (int kt = 0; kt < 4; kt++) {
#pragma unroll
      for (int pb = 0; pb < 8; pb++) {
        uint32_t bf[4];
        LDSM_X4_T(bf[0], bf[1], bf[2], bf[3],
                  v_b + (uint32_t)(kt * 16 * AS_ROW * 2) + pb * 32);
        MMA_16816(o[2 * pb],     pa[kt], bf[0], bf[1]);
        MMA_16816(o[2 * pb + 1], pa[kt], bf[2], bf[3]);
      }
    }
  }

  // Normalize, split hi/lo, store into g_obig = [oh | ol | oh]
  float inv0 = 1.f / l0, inv1 = 1.f / l1;
#pragma unroll
  for (int nt = 0; nt < 16; nt++) {
    int d = nt * 8 + q4 * 2;
#pragma unroll
    for (int hh = 0; hh < 2; hh++) {
      int r = (hh == 0) ? row0 : row1;
      float v0 = o[nt][hh * 2]     * (hh == 0 ? inv0 : inv1);
      float v1 = o[nt][hh * 2 + 1] * (hh == 0 ? inv0 : inv1);
      __half h0 = __float2half_rn(v0);
      __half h1 = __float2half_rn(v1);
      __half e0 = __float2half_rn(v0 - __half2float(h0));
      __half e1 = __float2half_rn(v1 - __half2float(h1));
      __half* base = g_obig + (size_t)(b * SEQ + r) * KBIG + h * HD + d;
      *(__half2*)(base)              = __halves2half2(h0, h1);
      *(__half2*)(base + DMODEL)     = __halves2half2(e0, e1);
      *(__half2*)(base + 2 * DMODEL) = __halves2half2(h0, h1);
    }
  }
}

// ---------------------------------------------------------------------------
// Launch
// ---------------------------------------------------------------------------
extern "C" void kernel_launch(void* const* d_in, const int* in_sizes, int n_in,
                              void* d_out, int out_size) {
  const float* x  = (const float*)d_in[0];
  const float* Wq = (const float*)d_in[1];
  const float* Wk = (const float*)d_in[2];
  const float* Wv = (const float*)d_in[3];
  const float* Wo = (const float*)d_in[4];
  const int* is_causal = (const int*)d_in[5];
  float* out = (float*)d_out;

  __half *xbig, *obig, *wt, *wot;
  cudaGetSymbolAddress((void**)&xbig, g_xbig);
  cudaGetSymbolAddress((void**)&obig, g_obig);
  cudaGetSymbolAddress((void**)&wt,  g_wt);
  cudaGetSymbolAddress((void**)&wot, g_wot);

  const int smem_bytes = 6 * STAGE_H * 2;  // 110592
  cudaFuncSetAttribute(gemm_f16_kernel<0>,
                       cudaFuncAttributeMaxDynamicSharedMemorySize, smem_bytes);
  cudaFuncSetAttribute(gemm_f16_kernel<3>,
                       cudaFuncAttributeMaxDynamicSharedMemorySize, smem_bytes);

  rope_init_kernel<<<(SEQ * 64 + 255) / 256, 256>>>();
  split_x_kernel<<<(MROWS * DMODEL) / 256, 256>>>(x);
  tsplit_w_kernel<<<dim3((NH * HD) / 32, DMODEL / 32), dim3(32, 8)>>>(
      Wq, wt, NH * HD);
  tsplit_w_kernel<<<dim3((NKV * HD) / 32, DMODEL / 32), dim3(32, 8)>>>(
      Wk, wt + (size_t)(NH * HD) * KBIG, NKV * HD);
  tsplit_w_kernel<<<dim3((NKV * HD) / 32, DMODEL / 32), dim3(32, 8)>>>(
      Wv, wt + (size_t)(NH * HD + NKV * HD) * KBIG, NKV * HD);
  tsplit_w_kernel<<<dim3(DMODEL / 32, DMODEL / 32), dim3(32, 8)>>>(Wo, wot, DMODEL);

  gemm_f16_kernel<0><<<dim3(NQKV / 128, MROWS / 128), 256, smem_bytes>>>(
      xbig, wt, nullptr);

  attn_kernel<<<dim3(SEQ / 128, NH, BATCH), 256>>>(is_causal);

  gemm_f16_kernel<3><<<dim3(DMODEL / 128, MROWS / 128), 256, smem_bytes>>>(
      obig, wot, out);
}

// round 7
// speedup vs baseline: 2.5805x; 1.0130x over previous
#include <cuda_runtime.h>
#include <cuda_fp16.h>
#include <math.h>
#include <stdint.h>

#define BATCH  2
#define SEQ    2048
#define DMODEL 2048
#define NH     16
#define NKV    8
#define HD     128
#define KBIG   (3 * DMODEL)   // 6144: [hi | lo | hi] split-K layout
#define MROWS  (BATCH * SEQ)  // 4096
#define NQKV   (NH * HD + 2 * NKV * HD)  // 4096 combined QKV columns

// ---------------------------------------------------------------------------
// Scratch (device globals; no allocation allowed)
// ---------------------------------------------------------------------------
__device__ __half g_xbig[(size_t)MROWS * KBIG];       // [m][6144] = [xh|xl|xh]
__device__ __half g_obig[(size_t)MROWS * KBIG];       // [m][6144] = [oh|ol|oh]
__device__ __half g_wt  [(size_t)NQKV * KBIG];        // [n][6144] = [Wh|Wh|Wl] (Q|K|V)
__device__ __half g_wot [(size_t)DMODEL * KBIG];
__device__ __half g_q[(size_t)BATCH * NH  * SEQ * HD];
__device__ __half g_k[(size_t)BATCH * NKV * SEQ * HD];
__device__ __half g_v[(size_t)BATCH * NKV * SEQ * HD];
__device__ float  g_cos[SEQ * (HD / 2)];
__device__ float  g_sin[SEQ * (HD / 2)];

// ---------------------------------------------------------------------------
// Helpers
// ---------------------------------------------------------------------------
__device__ __forceinline__ uint32_t pack_half2(float a, float b) {
  __half2 h = __floats2half2_rn(a, b);
  return *reinterpret_cast<uint32_t*>(&h);
}

#define MMA_16816(C, A, B0, B1)                                              \
  asm volatile(                                                              \
      "mma.sync.aligned.m16n8k16.row.col.f32.f16.f16.f32 "                   \
      "{%0,%1,%2,%3}, {%4,%5,%6,%7}, {%8,%9}, {%0,%1,%2,%3};\n"              \
      : "+f"((C)[0]), "+f"((C)[1]), "+f"((C)[2]), "+f"((C)[3])               \
      : "r"((A)[0]), "r"((A)[1]), "r"((A)[2]), "r"((A)[3]),                  \
        "r"(B0), "r"(B1))

#define LDSM_X4(R0, R1, R2, R3, ADDR)                                        \
  asm volatile(                                                              \
      "ldmatrix.sync.aligned.m8n8.x4.shared.b16 {%0,%1,%2,%3}, [%4];\n"      \
      : "=r"(R0), "=r"(R1), "=r"(R2), "=r"(R3) : "r"(ADDR))

#define LDSM_X4_T(R0, R1, R2, R3, ADDR)                                      \
  asm volatile(                                                              \
      "ldmatrix.sync.aligned.m8n8.x4.trans.shared.b16 {%0,%1,%2,%3}, [%4];\n"\
      : "=r"(R0), "=r"(R1), "=r"(R2), "=r"(R3) : "r"(ADDR))

#define CP_ASYNC16(DST, SRC)                                                 \
  asm volatile("cp.async.cg.shared.global [%0], [%1], 16;\n" ::              \
                   "r"(DST), "l"(SRC))
#define CP_COMMIT() asm volatile("cp.async.commit_group;\n")
#define CP_WAIT(N)  asm volatile("cp.async.wait_group %0;\n" ::"n"(N))

// ---------------------------------------------------------------------------
// Precompute kernels
// ---------------------------------------------------------------------------
__global__ void rope_init_kernel() {
  int idx = blockIdx.x * blockDim.x + threadIdx.x;
  if (idx < SEQ * (HD / 2)) {
    int s = idx >> 6;
    int i = idx & 63;
    float inv = (float)pow(10000.0, -(double)(2 * i) / (double)HD);
    float a = (float)s * inv;
    g_cos[idx] = cosf(a);
    g_sin[idx] = sinf(a);
  }
}

__global__ void split_x_kernel(const float* __restrict__ x) {
  int idx = blockIdx.x * blockDim.x + threadIdx.x;
  if (idx < MROWS * DMODEL) {
    int m = idx >> 11;
    int k = idx & (DMODEL - 1);
    float v = x[idx];
    __half h = __float2half_rn(v);
    __half l = __float2half_rn(v - __half2float(h));
    __half* row = g_xbig + (size_t)m * KBIG;
    row[k]              = h;
    row[DMODEL + k]     = l;
    row[2 * DMODEL + k] = h;
  }
}

// W[k][n] fp32 -> Wt[n] = [Wh | Wh | Wl]  (tiled transpose)
__global__ void tsplit_w_kernel(const float* __restrict__ W,
                                __half* __restrict__ Wt, int N) {
  __shared__ float tile[32][33];
  const int n0 = blockIdx.x * 32;
  const int k0 = blockIdx.y * 32;
  const int tx = threadIdx.x;
  const int ty = threadIdx.y;
#pragma unroll
  for (int j = 0; j < 32; j += 8)
    tile[ty + j][tx] = W[(size_t)(k0 + ty + j) * N + n0 + tx];
  __syncthreads();
#pragma unroll
  for (int j = 0; j < 32; j += 8) {
    int n = n0 + ty + j;
    int k = k0 + tx;
    float v = tile[tx][ty + j];
    __half h = __float2half_rn(v);
    __half l = __float2half_rn(v - __half2float(h));
    __half* row = Wt + (size_t)n * KBIG;
    row[k]              = h;
    row[DMODEL + k]     = h;
    row[2 * DMODEL + k] = l;
  }
}

// ---------------------------------------------------------------------------
// Pipelined fp16 GEMM: C[4096, N] = A[4096, KBIG] @ Bt[N, KBIG]^T
// Block 128x128, BK=64, 3-stage cp.async, 128 threads = 4 warps (2M x 2N),
// warp tile 64x64 (halves smem traffic per MAC vs 32x64).
// MODE 0: merged QKV epilogue (rope etc.)   MODE 3: out proj (fp32)
// ---------------------------------------------------------------------------
#define BK      64
#define STRIDE  72
#define STAGE_H (128 * STRIDE)
#define NITERS  (KBIG / BK)   // 96

template <int MODE>
__global__ __launch_bounds__(128) void gemm_f16_kernel(
    const __half* __restrict__ A, const __half* __restrict__ Bt,
    float* __restrict__ out) {
  extern __shared__ __align__(16) __half smem[];
  __half* As = smem;
  __half* Bs = smem + 3 * STAGE_H;

  const int tid  = threadIdx.x;
  const int wid  = tid >> 5;
  const int lane = tid & 31;
  const int wm   = wid >> 1;   // 0..1
  const int wn   = wid & 1;    // 0..1
  const int g    = lane >> 2;
  const int q4   = lane & 3;
  const int m0   = blockIdx.y * 128;
  const int n0   = blockIdx.x * 128;

  const uint32_t as_base = (uint32_t)__cvta_generic_to_shared(As);
  const uint32_t bs_base = (uint32_t)__cvta_generic_to_shared(Bs);

  const int crow = tid >> 3;   // 0..15
  const int cseg = tid & 7;

  const uint32_t a_off =
      (uint32_t)((wm * 64 + (lane & 15)) * STRIDE + (lane >> 4) * 8) * 2;
  const uint32_t b_off =
      (uint32_t)((wn * 64 + (lane & 7) + ((lane & 16) >> 1)) * STRIDE +
                 (lane & 8)) * 2;

  float c[4][8][4];
#pragma unroll
  for (int mt = 0; mt < 4; mt++)
#pragma unroll
    for (int nt = 0; nt < 8; nt++)
#pragma unroll
      for (int j = 0; j < 4; j++) c[mt][nt][j] = 0.f;

  auto load_stage = [&](int stg, int k0) {
    uint32_t abase = as_base + stg * STAGE_H * 2;
    uint32_t bbase = bs_base + stg * STAGE_H * 2;
#pragma unroll
    for (int j = 0; j < 8; j++) {
      int row = j * 16 + crow;
      uint32_t so = (uint32_t)(row * STRIDE + cseg * 8) * 2;
      CP_ASYNC16(abase + so, A + (size_t)(m0 + row) * KBIG + k0 + cseg * 8);
      CP_ASYNC16(bbase + so, Bt + (size_t)(n0 + row) * KBIG + k0 + cseg * 8);
    }
  };

  load_stage(0, 0);
  CP_COMMIT();
  load_stage(1, BK);
  CP_COMMIT();

  for (int it = 0; it < NITERS; it++) {
    CP_WAIT(1);
    __syncthreads();
    if (it + 2 < NITERS) load_stage((it + 2) % 3, (it + 2) * BK);
    CP_COMMIT();

    const int stg = it % 3;
    const uint32_t ab = as_base + stg * STAGE_H * 2 + a_off;
    const uint32_t bb = bs_base + stg * STAGE_H * 2 + b_off;
#pragma unroll
    for (int kt = 0; kt < 4; kt++) {
      const uint32_t ko = kt * 32;
      uint32_t a[4][4];
#pragma unroll
      for (int mt = 0; mt < 4; mt++)
        LDSM_X4(a[mt][0], a[mt][1], a[mt][2], a[mt][3],
                ab + (uint32_t)(mt * 16 * STRIDE * 2) + ko);
#pragma unroll
      for (int p = 0; p < 4; p++) {
        uint32_t b[4];
        LDSM_X4(b[0], b[1], b[2], b[3],
                bb + (uint32_t)(p * 16 * STRIDE * 2) + ko);
#pragma unroll
        for (int mt = 0; mt < 4; mt++) {
          MMA_16816(c[mt][2 * p],     a[mt], b[0], b[1]);
          MMA_16816(c[mt][2 * p + 1], a[mt], b[2], b[3]);
        }
      }
    }
  }

  const float qscale = 0.08838834764831845f;  // 1/sqrt(128)
#pragma unroll
  for (int mt = 0; mt < 4; mt++) {
#pragma unroll
    for (int nt = 0; nt < 8; nt++) {
      int col = n0 + wn * 64 + nt * 8 + q4 * 2;
      int row = m0 + wm * 64 + mt * 16 + g;
      if (MODE == 3) {
        *(float2*)&out[(size_t)row * DMODEL + col] =
            make_float2(c[mt][nt][0], c[mt][nt][1]);
        *(float2*)&out[(size_t)(row + 8) * DMODEL + col] =
            make_float2(c[mt][nt][2], c[mt][nt][3]);
      } else {
#pragma unroll
        for (int hh = 0; hh < 2; hh++) {
          int r = row + hh * 8;
          int b = r >> 11;
          int s = r & 2047;
          float v0 = c[mt][nt][hh * 2];
          float v1 = c[mt][nt][hh * 2 + 1];
          __half* dst;
          if (col < NH * HD) {            // Q: rope + scale
            int head = col >> 7, d = col & 127;
            int i    = d >> 1;
            float cs = g_cos[s * 64 + i], sn = g_sin[s * 64 + i];
            float r0 = v0 * cs - v1 * sn, r1 = v0 * sn + v1 * cs;
            v0 = r0 * qscale; v1 = r1 * qscale;
            dst = &g_q[(((size_t)(b * NH + head)) * SEQ + s) * HD + d];
          } else if (col < NH * HD + NKV * HD) {  // K: rope
            int kc = col - NH * HD;
            int head = kc >> 7, d = kc & 127;
            int i    = d >> 1;
            float cs = g_cos[s * 64 + i], sn = g_sin[s * 64 + i];
            float r0 = v0 * cs - v1 * sn, r1 = v0 * sn + v1 * cs;
            v0 = r0; v1 = r1;
            dst = &g_k[(((size_t)(b * NKV + head)) * SEQ + s) * HD + d];
          } else {                        // V
            int vc = col - NH * HD - NKV * HD;
            int head = vc >> 7, d = vc & 127;
            dst = &g_v[(((size_t)(b * NKV + head)) * SEQ + s) * HD + d];
          }
          *(__half2*)dst = __floats2half2_rn(v0, v1);
        }
      }
    }
  }
}

// ---------------------------------------------------------------------------
// Flash attention (round-5 proven version, verbatim): block = (128 Q rows,
// head, batch), 256 threads, synchronous K/V chunk loads of 64 rows.
// ---------------------------------------------------------------------------
#define AS_ROW 136   // halves per smem row

__global__ __launch_bounds__(256) void attn_kernel(const int* __restrict__ causal_flag) {
  __shared__ __align__(16) __half S[128 * AS_ROW];  // K rows 0-63, V rows 64-127

  const int tid  = threadIdx.x;
  const int wid  = tid >> 5;
  const int lane = tid & 31;
  const int g    = lane >> 2;
  const int q4   = lane & 3;
  const int qtile = blockIdx.x;
  const int h     = blockIdx.y;
  const int b     = blockIdx.z;
  const int kv    = h >> 1;
  const int qbase = qtile * 128;
  const int causal = *causal_flag;

  const uint32_t s_base = (uint32_t)__cvta_generic_to_shared(S);
  const uint32_t q_a = s_base +
      (uint32_t)((wid * 16 + (lane & 15)) * AS_ROW + (lane >> 4) * 8) * 2;
  const uint32_t k_b = s_base +
      (uint32_t)(((lane & 7) + ((lane & 16) >> 1)) * AS_ROW + (lane & 8)) * 2;
  const uint32_t v_b = s_base +
      (uint32_t)((64 + (lane & 15)) * AS_ROW + (lane >> 4) * 8) * 2;

  // Stage Q tile (128 x 128) and extract A fragments
  const __half* qp = g_q + (((size_t)(b * NH + h)) * SEQ + qbase) * HD;
#pragma unroll
  for (int j = 0; j < 8; j++) {
    int i   = j * 256 + tid;
    int row = i >> 4;
    int seg = i & 15;
    *(uint4*)&S[row * AS_ROW + seg * 8] = *(const uint4*)(qp + row * HD + seg * 8);
  }
  __syncthreads();
  uint32_t qa[8][4];
#pragma unroll
  for (int kt = 0; kt < 8; kt++)
    LDSM_X4(qa[kt][0], qa[kt][1], qa[kt][2], qa[kt][3], q_a + kt * 32);

  float o[16][4];
#pragma unroll
  for (int i = 0; i < 16; i++)
#pragma unroll
    for (int j = 0; j < 4; j++) o[i][j] = 0.f;
  float m0 = -1e30f, m1 = -1e30f, l0 = 0.f, l1 = 0.f;

  const int jend = causal ? (qbase + 128) : SEQ;
  const __half* kbp = g_k + ((size_t)(b * NKV + kv)) * SEQ * HD;
  const __half* vbp = g_v + ((size_t)(b * NKV + kv)) * SEQ * HD;
  const int row0 = qbase + wid * 16 + g;
  const int row1 = row0 + 8;

  for (int j0 = 0; j0 < jend; j0 += 64) {
    __syncthreads();  // previous chunk reads / Q frag extraction complete
#pragma unroll
    for (int j = 0; j < 4; j++) {
      int i   = j * 256 + tid;
      int row = i >> 4;
      int seg = i & 15;
      *(uint4*)&S[row * AS_ROW + seg * 8] =
          *(const uint4*)(kbp + (size_t)(j0 + row) * HD + seg * 8);
      *(uint4*)&S[(64 + row) * AS_ROW + seg * 8] =
          *(const uint4*)(vbp + (size_t)(j0 + row) * HD + seg * 8);
    }
    __syncthreads();

    // S = Q @ K^T : per warp 16 x 64
    float sc[8][4];
#pragma unroll
    for (int i = 0; i < 8; i++)
#pragma unroll
      for (int j = 0; j < 4; j++) sc[i][j] = 0.f;
#pragma unroll
    for (int kt = 0; kt < 8; kt++) {
#pragma unroll
      for (int p = 0; p < 4; p++) {
        uint32_t bf[4];
        LDSM_X4(bf[0], bf[1], bf[2], bf[3],
                k_b + (uint32_t)(p * 16 * AS_ROW * 2) + kt * 32);
        MMA_16816(sc[2 * p],     qa[kt], bf[0], bf[1]);
        MMA_16816(sc[2 * p + 1], qa[kt], bf[2], bf[3]);
      }
    }

    if (causal && j0 + 64 > qbase) {
#pragma unroll
      for (int nt = 0; nt < 8; nt++) {
        int col = j0 + nt * 8 + q4 * 2;
        if (col     > row0) sc[nt][0] = -1e30f;
        if (col + 1 > row0) sc[nt][1] = -1e30f;
        if (col     > row1) sc[nt][2] = -1e30f;
        if (col + 1 > row1) sc[nt][3] = -1e30f;
      }
    }

    float r0 = -1e30f, r1 = -1e30f;
#pragma unroll
    for (int nt = 0; nt < 8; nt++) {
      r0 = fmaxf(r0, fmaxf(sc[nt][0], sc[nt][1]));
      r1 = fmaxf(r1, fmaxf(sc[nt][2], sc[nt][3]));
    }
    r0 = fmaxf(r0, __shfl_xor_sync(0xffffffffu, r0, 1));
    r0 = fmaxf(r0, __shfl_xor_sync(0xffffffffu, r0, 2));
    r1 = fmaxf(r1, __shfl_xor_sync(0xffffffffu, r1, 1));
    r1 = fmaxf(r1, __shfl_xor_sync(0xffffffffu, r1, 2));
    float mn0 = fmaxf(m0, r0), mn1 = fmaxf(m1, r1);
    float sf0 = __expf(m0 - mn0), sf1 = __expf(m1 - mn1);
    m0 = mn0; m1 = mn1;
    float s0 = 0.f, s1 = 0.f;
#pragma unroll
    for (int nt = 0; nt < 8; nt++) {
      sc[nt][0] = __expf(sc[nt][0] - mn0);
      sc[nt][1] = __expf(sc[nt][1] - mn0);
      sc[nt][2] = __expf(sc[nt][2] - mn1);
      sc[nt][3] = __expf(sc[nt][3] - mn1);
      s0 += sc[nt][0] + sc[nt][1];
      s1 += sc[nt][2] + sc[nt][3];
    }
    s0 += __shfl_xor_sync(0xffffffffu, s0, 1);
    s0 += __shfl_xor_sync(0xffffffffu, s0, 2);
    s1 += __shfl_xor_sync(0xffffffffu, s1, 1);
    s1 += __shfl_xor_sync(0xffffffffu, s1, 2);
    l0 = l0 * sf0 + s0;
    l1 = l1 * sf1 + s1;
#pragma unroll
    for (int i = 0; i < 16; i++) {
      o[i][0] *= sf0; o[i][1] *= sf0;
      o[i][2] *= sf1; o[i][3] *= sf1;
    }

    uint32_t pa[4][4];
#pragma unroll
    for (int kt = 0; kt < 4; kt++) {
      pa[kt][0] = pack_half2(sc[2 * kt][0], sc[2 * kt][1]);
      pa[kt][1] = pack_half2(sc[2 * kt][2], sc[2 * kt][3]);
      pa[kt][2] = pack_half2(sc[2 * kt + 1][0], sc[2 * kt + 1][1]);
      pa[kt][3] = pack_half2(sc[2 * kt + 1][2], sc[2 * kt + 1][3]);
    }

    // O += P @ V : V B-fragments via ldmatrix.trans from natural [s][d]
#pragma unroll
    for (int kt = 0; kt < 4; kt++) {
#pragma unroll
      for (int pb = 0; pb < 8; pb++) {
        uint32_t bf[4];
        LDSM_X4_T(bf[0], bf[1], bf[2], bf[3],
                  v_b + (uint32_t)(kt * 16 * AS_ROW * 2) + pb * 32);
        MMA_16816(o[2 * pb],     pa[kt], bf[0], bf[1]);
        MMA_16816(o[2 * pb + 1], pa[kt], bf[2], bf[3]);
      }
    }
  }

  // Normalize, split hi/lo, store into g_obig = [oh | ol | oh]
  float inv0 = 1.f / l0, inv1 = 1.f / l1;
#pragma unroll
  for (int nt = 0; nt < 16; nt++) {
    int d = nt * 8 + q4 * 2;
#pragma unroll
    for (int hh = 0; hh < 2; hh++) {
      int r = (hh == 0) ? row0 : row1;
      float v0 = o[nt][hh * 2]     * (hh == 0 ? inv0 : inv1);
      float v1 = o[nt][hh * 2 + 1] * (hh == 0 ? inv0 : inv1);
      __half h0 = __float2half_rn(v0);
      __half h1 = __float2half_rn(v1);
      __half e0 = __float2half_rn(v0 - __half2float(h0));
      __half e1 = __float2half_rn(v1 - __half2float(h1));
      __half* base = g_obig + (size_t)(b * SEQ + r) * KBIG + h * HD + d;
      *(__half2*)(base)              = __halves2half2(h0, h1);
      *(__half2*)(base + DMODEL)     = __halves2half2(e0, e1);
      *(__half2*)(base + 2 * DMODEL) = __halves2half2(h0, h1);
    }
  }
}

// ---------------------------------------------------------------------------
// Launch
// ---------------------------------------------------------------------------
extern "C" void kernel_launch(void* const* d_in, const int* in_sizes, int n_in,
                              void* d_out, int out_size) {
  const float* x  = (const float*)d_in[0];
  const float* Wq = (const float*)d_in[1];
  const float* Wk = (const float*)d_in[2];
  const float* Wv = (const float*)d_in[3];
  const float* Wo = (const float*)d_in[4];
  const int* is_causal = (const int*)d_in[5];
  float* out = (float*)d_out;

  __half *xbig, *obig, *wt, *wot;
  cudaGetSymbolAddress((void**)&xbig, g_xbig);
  cudaGetSymbolAddress((void**)&obig, g_obig);
  cudaGetSymbolAddress((void**)&wt,  g_wt);
  cudaGetSymbolAddress((void**)&wot, g_wot);

  const int gemm_smem = 6 * STAGE_H * 2;   // 110592
  cudaFuncSetAttribute(gemm_f16_kernel<0>,
                       cudaFuncAttributeMaxDynamicSharedMemorySize, gemm_smem);
  cudaFuncSetAttribute(gemm_f16_kernel<3>,
                       cudaFuncAttributeMaxDynamicSharedMemorySize, gemm_smem);

  rope_init_kernel<<<(SEQ * 64 + 255) / 256, 256>>>();
  split_x_kernel<<<(MROWS * DMODEL) / 256, 256>>>(x);
  tsplit_w_kernel<<<dim3((NH * HD) / 32, DMODEL / 32), dim3(32, 8)>>>(
      Wq, wt, NH * HD);
  tsplit_w_kernel<<<dim3((NKV * HD) / 32, DMODEL / 32), dim3(32, 8)>>>(
      Wk, wt + (size_t)(NH * HD) * KBIG, NKV * HD);
  tsplit_w_kernel<<<dim3((NKV * HD) / 32, DMODEL / 32), dim3(32, 8)>>>(
      Wv, wt + (size_t)(NH * HD + NKV * HD) * KBIG, NKV * HD);
  tsplit_w_kernel<<<dim3(DMODEL / 32, DMODEL / 32), dim3(32, 8)>>>(Wo, wot, DMODEL);

  gemm_f16_kernel<0><<<dim3(NQKV / 128, MROWS / 128), 128, gemm_smem>>>(
      xbig, wt, nullptr);

  attn_kernel<<<dim3(SEQ / 128, NH, BATCH), 256>>>(is_causal);

  gemm_f16_kernel<3><<<dim3(DMODEL / 128, MROWS / 128), 128, gemm_smem>>>(
      obig, wot, out);
}

// round 8
// speedup vs baseline: 3.4807x; 1.3488x over previous
#include <cuda_runtime.h>
#include <cuda_fp16.h>
#include <math.h>
#include <stdint.h>

#define BATCH  2
#define SEQ    2048
#define DMODEL 2048
#define NH     16
#define NKV    8
#define HD     128
#define KBIG   (2 * DMODEL)   // 4096: [hi | lo] split-K layout (A exact, W fp16)
#define MROWS  (BATCH * SEQ)  // 4096
#define NQKV   (NH * HD + 2 * NKV * HD)  // 4096 combined QKV columns

// ---------------------------------------------------------------------------
// Scratch (device globals; no allocation allowed)
// ---------------------------------------------------------------------------
__device__ __half g_xbig[(size_t)MROWS * KBIG];       // [m][4096] = [xh|xl]
__device__ __half g_obig[(size_t)MROWS * KBIG];       // [m][4096] = [oh|ol]
__device__ __half g_wt  [(size_t)NQKV * KBIG];        // [n][4096] = [Wh|Wh] (Q|K|V)
__device__ __half g_wot [(size_t)DMODEL * KBIG];
__device__ __half g_q[(size_t)BATCH * NH  * SEQ * HD];
__device__ __half g_k[(size_t)BATCH * NKV * SEQ * HD];
__device__ __half g_v[(size_t)BATCH * NKV * SEQ * HD];
__device__ float  g_cos[SEQ * (HD / 2)];
__device__ float  g_sin[SEQ * (HD / 2)];

// ---------------------------------------------------------------------------
// Helpers
// ---------------------------------------------------------------------------
__device__ __forceinline__ uint32_t pack_half2(float a, float b) {
  __half2 h = __floats2half2_rn(a, b);
  return *reinterpret_cast<uint32_t*>(&h);
}

#define MMA_16816(C, A, B0, B1)                                              \
  asm volatile(                                                              \
      "mma.sync.aligned.m16n8k16.row.col.f32.f16.f16.f32 "                   \
      "{%0,%1,%2,%3}, {%4,%5,%6,%7}, {%8,%9}, {%0,%1,%2,%3};\n"              \
      : "+f"((C)[0]), "+f"((C)[1]), "+f"((C)[2]), "+f"((C)[3])               \
      : "r"((A)[0]), "r"((A)[1]), "r"((A)[2]), "r"((A)[3]),                  \
        "r"(B0), "r"(B1))

#define LDSM_X4(R0, R1, R2, R3, ADDR)                                        \
  asm volatile(                                                              \
      "ldmatrix.sync.aligned.m8n8.x4.shared.b16 {%0,%1,%2,%3}, [%4];\n"      \
      : "=r"(R0), "=r"(R1), "=r"(R2), "=r"(R3) : "r"(ADDR))

#define LDSM_X4_T(R0, R1, R2, R3, ADDR)                                      \
  asm volatile(                                                              \
      "ldmatrix.sync.aligned.m8n8.x4.trans.shared.b16 {%0,%1,%2,%3}, [%4];\n"\
      : "=r"(R0), "=r"(R1), "=r"(R2), "=r"(R3) : "r"(ADDR))

#define CP_ASYNC16(DST, SRC)                                                 \
  asm volatile("cp.async.cg.shared.global [%0], [%1], 16;\n" ::              \
                   "r"(DST), "l"(SRC))
#define CP_COMMIT() asm volatile("cp.async.commit_group;\n")
#define CP_WAIT(N)  asm volatile("cp.async.wait_group %0;\n" ::"n"(N))

// ---------------------------------------------------------------------------
// Precompute kernels
// ---------------------------------------------------------------------------
__global__ void rope_init_kernel() {
  int idx = blockIdx.x * blockDim.x + threadIdx.x;
  if (idx < SEQ * (HD / 2)) {
    int s = idx >> 6;
    int i = idx & 63;
    float inv = (float)pow(10000.0, -(double)(2 * i) / (double)HD);
    float a = (float)s * inv;
    g_cos[idx] = cosf(a);
    g_sin[idx] = sinf(a);
  }
}

// x[m][k] fp32 -> g_xbig[m] = [xh | xl]  (exact 2-term representation of x)
__global__ void split_x_kernel(const float* __restrict__ x) {
  int idx = blockIdx.x * blockDim.x + threadIdx.x;
  if (idx < MROWS * DMODEL) {
    int m = idx >> 11;
    int k = idx & (DMODEL - 1);
    float v = x[idx];
    __half h = __float2half_rn(v);
    __half l = __float2half_rn(v - __half2float(h));
    __half* row = g_xbig + (size_t)m * KBIG;
    row[k]          = h;
    row[DMODEL + k] = l;
  }
}

// W[k][n] fp32 -> Wt[n] = [Wh | Wh]  (tiled transpose; W quantized to fp16)
__global__ void tsplit_w_kernel(const float* __restrict__ W,
                                __half* __restrict__ Wt, int N) {
  __shared__ float tile[32][33];
  const int n0 = blockIdx.x * 32;
  const int k0 = blockIdx.y * 32;
  const int tx = threadIdx.x;
  const int ty = threadIdx.y;
#pragma unroll
  for (int j = 0; j < 32; j += 8)
    tile[ty + j][tx] = W[(size_t)(k0 + ty + j) * N + n0 + tx];
  __syncthreads();
#pragma unroll
  for (int j = 0; j < 32; j += 8) {
    int n = n0 + ty + j;
    int k = k0 + tx;
    __half h = __float2half_rn(tile[tx][ty + j]);
    __half* row = Wt + (size_t)n * KBIG;
    row[k]          = h;
    row[DMODEL + k] = h;
  }
}

// ---------------------------------------------------------------------------
// Pipelined fp16 GEMM: C[4096, N] = A[4096, KBIG] @ Bt[N, KBIG]^T
// Block 128x128, BK=64, 3-stage cp.async, 128 threads = 4 warps (2M x 2N),
// warp tile 64x64.
// MODE 0: merged QKV epilogue (rope etc.)   MODE 3: out proj (fp32)
// ---------------------------------------------------------------------------
#define BK      64
#define STRIDE  72
#define STAGE_H (128 * STRIDE)
#define NITERS  (KBIG / BK)   // 64

template <int MODE>
__global__ __launch_bounds__(128) void gemm_f16_kernel(
    const __half* __restrict__ A, const __half* __restrict__ Bt,
    float* __restrict__ out) {
  extern __shared__ __align__(16) __half smem[];
  __half* As = smem;
  __half* Bs = smem + 3 * STAGE_H;

  const int tid  = threadIdx.x;
  const int wid  = tid >> 5;
  const int lane = tid & 31;
  const int wm   = wid >> 1;   // 0..1
  const int wn   = wid & 1;    // 0..1
  const int g    = lane >> 2;
  const int q4   = lane & 3;
  const int m0   = blockIdx.y * 128;
  const int n0   = blockIdx.x * 128;

  const uint32_t as_base = (uint32_t)__cvta_generic_to_shared(As);
  const uint32_t bs_base = (uint32_t)__cvta_generic_to_shared(Bs);

  const int crow = tid >> 3;   // 0..15
  const int cseg = tid & 7;

  const uint32_t a_off =
      (uint32_t)((wm * 64 + (lane & 15)) * STRIDE + (lane >> 4) * 8) * 2;
  const uint32_t b_off =
      (uint32_t)((wn * 64 + (lane & 7) + ((lane & 16) >> 1)) * STRIDE +
                 (lane & 8)) * 2;

  float c[4][8][4];
#pragma unroll
  for (int mt = 0; mt < 4; mt++)
#pragma unroll
    for (int nt = 0; nt < 8; nt++)
#pragma unroll
      for (int j = 0; j < 4; j++) c[mt][nt][j] = 0.f;

  auto load_stage = [&](int stg, int k0) {
    uint32_t abase = as_base + stg * STAGE_H * 2;
    uint32_t bbase = bs_base + stg * STAGE_H * 2;
#pragma unroll
    for (int j = 0; j < 8; j++) {
      int row = j * 16 + crow;
      uint32_t so = (uint32_t)(row * STRIDE + cseg * 8) * 2;
      CP_ASYNC16(abase + so, A + (size_t)(m0 + row) * KBIG + k0 + cseg * 8);
      CP_ASYNC16(bbase + so, Bt + (size_t)(n0 + row) * KBIG + k0 + cseg * 8);
    }
  };

  load_stage(0, 0);
  CP_COMMIT();
  load_stage(1, BK);
  CP_COMMIT();

  for (int it = 0; it < NITERS; it++) {
    CP_WAIT(1);
    __syncthreads();
    if (it + 2 < NITERS) load_stage((it + 2) % 3, (it + 2) * BK);
    CP_COMMIT();

    const int stg = it % 3;
    const uint32_t ab = as_base + stg * STAGE_H * 2 + a_off;
    const uint32_t bb = bs_base + stg * STAGE_H * 2 + b_off;
#pragma unroll
    for (int kt = 0; kt < 4; kt++) {
      const uint32_t ko = kt * 32;
      uint32_t a[4][4];
#pragma unroll
      for (int mt = 0; mt < 4; mt++)
        LDSM_X4(a[mt][0], a[mt][1], a[mt][2], a[mt][3],
                ab + (uint32_t)(mt * 16 * STRIDE * 2) + ko);
#pragma unroll
      for (int p = 0; p < 4; p++) {
        uint32_t b[4];
        LDSM_X4(b[0], b[1], b[2], b[3],
                bb + (uint32_t)(p * 16 * STRIDE * 2) + ko);
#pragma unroll
        for (int mt = 0; mt < 4; mt++) {
          MMA_16816(c[mt][2 * p],     a[mt], b[0], b[1]);
          MMA_16816(c[mt][2 * p + 1], a[mt], b[2], b[3]);
        }
      }
    }
  }

  const float qscale = 0.08838834764831845f;  // 1/sqrt(128)
#pragma unroll
  for (int mt = 0; mt < 4; mt++) {
#pragma unroll
    for (int nt = 0; nt < 8; nt++) {
      int col = n0 + wn * 64 + nt * 8 + q4 * 2;
      int row = m0 + wm * 64 + mt * 16 + g;
      if (MODE == 3) {
        *(float2*)&out[(size_t)row * DMODEL + col] =
            make_float2(c[mt][nt][0], c[mt][nt][1]);
        *(float2*)&out[(size_t)(row + 8) * DMODEL + col] =
            make_float2(c[mt][nt][2], c[mt][nt][3]);
      } else {
#pragma unroll
        for (int hh = 0; hh < 2; hh++) {
          int r = row + hh * 8;
          int b = r >> 11;
          int s = r & 2047;
          float v0 = c[mt][nt][hh * 2];
          float v1 = c[mt][nt][hh * 2 + 1];
          __half* dst;
          if (col < NH * HD) {            // Q: rope + scale
            int head = col >> 7, d = col & 127;
            int i    = d >> 1;
            float cs = g_cos[s * 64 + i], sn = g_sin[s * 64 + i];
            float r0 = v0 * cs - v1 * sn, r1 = v0 * sn + v1 * cs;
            v0 = r0 * qscale; v1 = r1 * qscale;
            dst = &g_q[(((size_t)(b * NH + head)) * SEQ + s) * HD + d];
          } else if (col < NH * HD + NKV * HD) {  // K: rope
            int kc = col - NH * HD;
            int head = kc >> 7, d = kc & 127;
            int i    = d >> 1;
            float cs = g_cos[s * 64 + i], sn = g_sin[s * 64 + i];
            float r0 = v0 * cs - v1 * sn, r1 = v0 * sn + v1 * cs;
            v0 = r0; v1 = r1;
            dst = &g_k[(((size_t)(b * NKV + head)) * SEQ + s) * HD + d];
          } else {                        // V
            int vc = col - NH * HD - NKV * HD;
            int head = vc >> 7, d = vc & 127;
            dst = &g_v[(((size_t)(b * NKV + head)) * SEQ + s) * HD + d];
          }
          *(__half2*)dst = __floats2half2_rn(v0, v1);
        }
      }
    }
  }
}

// ---------------------------------------------------------------------------
// Flash attention (proven version): block = (128 Q rows, head, batch),
// 256 threads, synchronous K/V chunk loads of 64 rows.
// ---------------------------------------------------------------------------
#define AS_ROW 136   // halves per smem row

__global__ __launch_bounds__(256) void attn_kernel(const int* __restrict__ causal_flag) {
  __shared__ __align__(16) __half S[128 * AS_ROW];  // K rows 0-63, V rows 64-127

  const int tid  = threadIdx.x;
  const int wid  = tid >> 5;
  const int lane = tid & 31;
  const int g    = lane >> 2;
  const int q4   = lane & 3;
  const int qtile = blockIdx.x;
  const int h     = blockIdx.y;
  const int b     = blockIdx.z;
  const int kv    = h >> 1;
  const int qbase = qtile * 128;
  const int causal = *causal_flag;

  const uint32_t s_base = (uint32_t)__cvta_generic_to_shared(S);
  const uint32_t q_a = s_base +
      (uint32_t)((wid * 16 + (lane & 15)) * AS_ROW + (lane >> 4) * 8) * 2;
  const uint32_t k_b = s_base +
      (uint32_t)(((lane & 7) + ((lane & 16) >> 1)) * AS_ROW + (lane & 8)) * 2;
  const uint32_t v_b = s_base +
      (uint32_t)((64 + (lane & 15)) * AS_ROW + (lane >> 4) * 8) * 2;

  // Stage Q tile (128 x 128) and extract A fragments
  const __half* qp = g_q + (((size_t)(b * NH + h)) * SEQ + qbase) * HD;
#pragma unroll
  for (int j = 0; j < 8; j++) {
    int i   = j * 256 + tid;
    int row = i >> 4;
    int seg = i & 15;
    *(uint4*)&S[row * AS_ROW + seg * 8] = *(const uint4*)(qp + row * HD + seg * 8);
  }
  __syncthreads();
  uint32_t qa[8][4];
#pragma unroll
  for (int kt = 0; kt < 8; kt++)
    LDSM_X4(qa[kt][0], qa[kt][1], qa[kt][2], qa[kt][3], q_a + kt * 32);

  float o[16][4];
#pragma unroll
  for (int i = 0; i < 16; i++)
#pragma unroll
    for (int j = 0; j < 4; j++) o[i][j] = 0.f;
  float m0 = -1e30f, m1 = -1e30f, l0 = 0.f, l1 = 0.f;

  const int jend = causal ? (qbase + 128) : SEQ;
  const __half* kbp = g_k + ((size_t)(b * NKV + kv)) * SEQ * HD;
  const __half* vbp = g_v + ((size_t)(b * NKV + kv)) * SEQ * HD;
  const int row0 = qbase + wid * 16 + g;
  const int row1 = row0 + 8;

  for (int j0 = 0; j0 < jend; j0 += 64) {
    __syncthreads();  // previous chunk reads / Q frag extraction complete
#pragma unroll
    for (int j = 0; j < 4; j++) {
      int i   = j * 256 + tid;
      int row = i >> 4;
      int seg = i & 15;
      *(uint4*)&S[row * AS_ROW + seg * 8] =
          *(const uint4*)(kbp + (size_t)(j0 + row) * HD + seg * 8);
      *(uint4*)&S[(64 + row) * AS_ROW + seg * 8] =
          *(const uint4*)(vbp + (size_t)(j0 + row) * HD + seg * 8);
    }
    __syncthreads();

    // S = Q @ K^T : per warp 16 x 64
    float sc[8][4];
#pragma unroll
    for (int i = 0; i < 8; i++)
#pragma unroll
      for (int j = 0; j < 4; j++) sc[i][j] = 0.f;
#pragma unroll
    for (int kt = 0; kt < 8; kt++) {
#pragma unroll
      for (int p = 0; p < 4; p++) {
        uint32_t bf[4];
        LDSM_X4(bf[0], bf[1], bf[2], bf[3],
                k_b + (uint32_t)(p * 16 * AS_ROW * 2) + kt * 32);
        MMA_16816(sc[2 * p],     qa[kt], bf[0], bf[1]);
        MMA_16816(sc[2 * p + 1], qa[kt], bf[2], bf[3]);
      }
    }

    if (causal && j0 + 64 > qbase) {
#pragma unroll
      for (int nt = 0; nt < 8; nt++) {
        int col = j0 + nt * 8 + q4 * 2;
        if (col     > row0) sc[nt][0] = -1e30f;
        if (col + 1 > row0) sc[nt][1] = -1e30f;
        if (col     > row1) sc[nt][2] = -1e30f;
        if (col + 1 > row1) sc[nt][3] = -1e30f;
      }
    }

    float r0 = -1e30f, r1 = -1e30f;
#pragma unroll
    for (int nt = 0; nt < 8; nt++) {
      r0 = fmaxf(r0, fmaxf(sc[nt][0], sc[nt][1]));
      r1 = fmaxf(r1, fmaxf(sc[nt][2], sc[nt][3]));
    }
    r0 = fmaxf(r0, __shfl_xor_sync(0xffffffffu, r0, 1));
    r0 = fmaxf(r0, __shfl_xor_sync(0xffffffffu, r0, 2));
    r1 = fmaxf(r1, __shfl_xor_sync(0xffffffffu, r1, 1));
    r1 = fmaxf(r1, __shfl_xor_sync(0xffffffffu, r1, 2));
    float mn0 = fmaxf(m0, r0), mn1 = fmaxf(m1, r1);
    float sf0 = __expf(m0 - mn0), sf1 = __expf(m1 - mn1);
    m0 = mn0; m1 = mn1;
    float s0 = 0.f, s1 = 0.f;
#pragma unroll
    for (int nt = 0; nt < 8; nt++) {
      sc[nt][0] = __expf(sc[nt][0] - mn0);
      sc[nt][1] = __expf(sc[nt][1] - mn0);
      sc[nt][2] = __expf(sc[nt][2] - mn1);
      sc[nt][3] = __expf(sc[nt][3] - mn1);
      s0 += sc[nt][0] + sc[nt][1];
      s1 += sc[nt][2] + sc[nt][3];
    }
    s0 += __shfl_xor_sync(0xffffffffu, s0, 1);
    s0 += __shfl_xor_sync(0xffffffffu, s0, 2);
    s1 += __shfl_xor_sync(0xffffffffu, s1, 1);
    s1 += __shfl_xor_sync(0xffffffffu, s1, 2);
    l0 = l0 * sf0 + s0;
    l1 = l1 * sf1 + s1;
#pragma unroll
    for (int i = 0; i < 16; i++) {
      o[i][0] *= sf0; o[i][1] *= sf0;
      o[i][2] *= sf1; o[i][3] *= sf1;
    }

    uint32_t pa[4][4];
#pragma unroll
    for (int kt = 0; kt < 4; kt++) {
      pa[kt][0] = pack_half2(sc[2 * kt][0], sc[2 * kt][1]);
      pa[kt][1] = pack_half2(sc[2 * kt][2], sc[2 * kt][3]);
      pa[kt][2] = pack_half2(sc[2 * kt + 1][0], sc[2 * kt + 1][1]);
      pa[kt][3] = pack_half2(sc[2 * kt + 1][2], sc[2 * kt + 1][3]);
    }

    // O += P @ V : V B-fragments via ldmatrix.trans from natural [s][d]
#pragma unroll
    for (int kt = 0; kt < 4; kt++) {
#pragma unroll
      for (int pb = 0; pb < 8; pb++) {
        uint32_t bf[4];
        LDSM_X4_T(bf[0], bf[1], bf[2], bf[3],
                  v_b + (uint32_t)(kt * 16 * AS_ROW * 2) + pb * 32);
        MMA_16816(o[2 * pb],     pa[kt], bf[0], bf[1]);
        MMA_16816(o[2 * pb + 1], pa[kt], bf[2], bf[3]);
      }
    }
  }

  // Normalize, split hi/lo, store into g_obig = [oh | ol]
  float inv0 = 1.f / l0, inv1 = 1.f / l1;
#pragma unroll
  for (int nt = 0; nt < 16; nt++) {
    int d = nt * 8 + q4 * 2;
#pragma unroll
    for (int hh = 0; hh < 2; hh++) {
      int r = (hh == 0) ? row0 : row1;
      float v0 = o[nt][hh * 2]     * (hh == 0 ? inv0 : inv1);
      float v1 = o[nt][hh * 2 + 1] * (hh == 0 ? inv0 : inv1);
      __half h0 = __float2half_rn(v0);
      __half h1 = __float2half_rn(v1);
      __half e0 = __float2half_rn(v0 - __half2float(h0));
      __half e1 = __float2half_rn(v1 - __half2float(h1));
      __half* base = g_obig + (size_t)(b * SEQ + r) * KBIG + h * HD + d;
      *(__half2*)(base)          = __halves2half2(h0, h1);
      *(__half2*)(base + DMODEL) = __halves2half2(e0, e1);
    }
  }
}

// ---------------------------------------------------------------------------
// Launch
// ---------------------------------------------------------------------------
extern "C" void kernel_launch(void* const* d_in, const int* in_sizes, int n_in,
                              void* d_out, int out_size) {
  const float* x  = (const float*)d_in[0];
  const float* Wq = (const float*)d_in[1];
  const float* Wk = (const float*)d_in[2];
  const float* Wv = (const float*)d_in[3];
  const float* Wo = (const float*)d_in[4];
  const int* is_causal = (const int*)d_in[5];
  float* out = (float*)d_out;

  __half *xbig, *obig, *wt, *wot;
  cudaGetSymbolAddress((void**)&xbig, g_xbig);
  cudaGetSymbolAddress((void**)&obig, g_obig);
  cudaGetSymbolAddress((void**)&wt,  g_wt);
  cudaGetSymbolAddress((void**)&wot, g_wot);

  const int gemm_smem = 6 * STAGE_H * 2;   // 110592
  cudaFuncSetAttribute(gemm_f16_kernel<0>,
                       cudaFuncAttributeMaxDynamicSharedMemorySize, gemm_smem);
  cudaFuncSetAttribute(gemm_f16_kernel<3>,
                       cudaFuncAttributeMaxDynamicSharedMemorySize, gemm_smem);

  rope_init_kernel<<<(SEQ * 64 + 255) / 256, 256>>>();
  split_x_kernel<<<(MROWS * DMODEL) / 256, 256>>>(x);
  tsplit_w_kernel<<<dim3((NH * HD) / 32, DMODEL / 32), dim3(32, 8)>>>(
      Wq, wt, NH * HD);
  tsplit_w_kernel<<<dim3((NKV * HD) / 32, DMODEL / 32), dim3(32, 8)>>>(
      Wk, wt + (size_t)(NH * HD) * KBIG, NKV * HD);
  tsplit_w_kernel<<<dim3((NKV * HD) / 32, DMODEL / 32), dim3(32, 8)>>>(
      Wv, wt + (size_t)(NH * HD + NKV * HD) * KBIG, NKV * HD);
  tsplit_w_kernel<<<dim3(DMODEL / 32, DMODEL / 32), dim3(32, 8)>>>(Wo, wot, DMODEL);

  gemm_f16_kernel<0><<<dim3(NQKV / 128, MROWS / 128), 128, gemm_smem>>>(
      xbig, wt, nullptr);

  attn_kernel<<<dim3(SEQ / 128, NH, BATCH), 256>>>(is_causal);

  gemm_f16_kernel<3><<<dim3(DMODEL / 128, MROWS / 128), 128, gemm_smem>>>(
      obig, wot, out);
}

// round 9
// speedup vs baseline: 3.5313x; 1.0145x over previous
#include <cuda_runtime.h>
#include <cuda_fp16.h>
#include <math.h>
#include <stdint.h>

#define BATCH  2
#define SEQ    2048
#define DMODEL 2048
#define NH     16
#define NKV    8
#define HD     128
#define KBIG   (2 * DMODEL)   // 4096: [hi | lo] split-K layout (A exact, W fp16)
#define MROWS  (BATCH * SEQ)  // 4096
#define NQKV   (NH * HD + 2 * NKV * HD)  // 4096 combined QKV columns

// ---------------------------------------------------------------------------
// Scratch (device globals; no allocation allowed)
// ---------------------------------------------------------------------------
__device__ __half g_xbig[(size_t)MROWS * KBIG];       // [m][4096] = [xh|xl]
__device__ __half g_obig[(size_t)MROWS * KBIG];       // [m][4096] = [oh|ol]
__device__ __half g_wt  [(size_t)NQKV * KBIG];        // [n][4096] = [Wh|Wh] (Q|K|V)
__device__ __half g_wot [(size_t)DMODEL * KBIG];
__device__ __half g_q[(size_t)BATCH * NH  * SEQ * HD];
__device__ __half g_k[(size_t)BATCH * NKV * SEQ * HD];
__device__ __half g_v[(size_t)BATCH * NKV * SEQ * HD];
__device__ float  g_cos[SEQ * (HD / 2)];
__device__ float  g_sin[SEQ * (HD / 2)];

// ---------------------------------------------------------------------------
// Helpers
// ---------------------------------------------------------------------------
__device__ __forceinline__ uint32_t pack_half2(float a, float b) {
  __half2 h = __floats2half2_rn(a, b);
  return *reinterpret_cast<uint32_t*>(&h);
}

#define MMA_16816(C, A, B0, B1)                                              \
  asm volatile(                                                              \
      "mma.sync.aligned.m16n8k16.row.col.f32.f16.f16.f32 "                   \
      "{%0,%1,%2,%3}, {%4,%5,%6,%7}, {%8,%9}, {%0,%1,%2,%3};\n"              \
      : "+f"((C)[0]), "+f"((C)[1]), "+f"((C)[2]), "+f"((C)[3])               \
      : "r"((A)[0]), "r"((A)[1]), "r"((A)[2]), "r"((A)[3]),                  \
        "r"(B0), "r"(B1))

#define LDSM_X4(R0, R1, R2, R3, ADDR)                                        \
  asm volatile(                                                              \
      "ldmatrix.sync.aligned.m8n8.x4.shared.b16 {%0,%1,%2,%3}, [%4];\n"      \
      : "=r"(R0), "=r"(R1), "=r"(R2), "=r"(R3) : "r"(ADDR))

#define LDSM_X4_T(R0, R1, R2, R3, ADDR)                                      \
  asm volatile(                                                              \
      "ldmatrix.sync.aligned.m8n8.x4.trans.shared.b16 {%0,%1,%2,%3}, [%4];\n"\
      : "=r"(R0), "=r"(R1), "=r"(R2), "=r"(R3) : "r"(ADDR))

#define CP_ASYNC16(DST, SRC)                                                 \
  asm volatile("cp.async.cg.shared.global [%0], [%1], 16;\n" ::              \
                   "r"(DST), "l"(SRC))
#define CP_COMMIT() asm volatile("cp.async.commit_group;\n")
#define CP_WAIT(N)  asm volatile("cp.async.wait_group %0;\n" ::"n"(N))

// ---------------------------------------------------------------------------
// Precompute kernels
// ---------------------------------------------------------------------------
__global__ void rope_init_kernel() {
  int idx = blockIdx.x * blockDim.x + threadIdx.x;
  if (idx < SEQ * (HD / 2)) {
    int s = idx >> 6;
    int i = idx & 63;
    float inv = (float)pow(10000.0, -(double)(2 * i) / (double)HD);
    float a = (float)s * inv;
    g_cos[idx] = cosf(a);
    g_sin[idx] = sinf(a);
  }
}

// x[m][k] fp32 -> g_xbig[m] = [xh | xl]  (exact 2-term representation of x)
__global__ void split_x_kernel(const float* __restrict__ x) {
  int idx = blockIdx.x * blockDim.x + threadIdx.x;
  if (idx < MROWS * DMODEL) {
    int m = idx >> 11;
    int k = idx & (DMODEL - 1);
    float v = x[idx];
    __half h = __float2half_rn(v);
    __half l = __float2half_rn(v - __half2float(h));
    __half* row = g_xbig + (size_t)m * KBIG;
    row[k]          = h;
    row[DMODEL + k] = l;
  }
}

// W[k][n] fp32 -> Wt[n] = [Wh | Wh]  (tiled transpose; W quantized to fp16)
__global__ void tsplit_w_kernel(const float* __restrict__ W,
                                __half* __restrict__ Wt, int N) {
  __shared__ float tile[32][33];
  const int n0 = blockIdx.x * 32;
  const int k0 = blockIdx.y * 32;
  const int tx = threadIdx.x;
  const int ty = threadIdx.y;
#pragma unroll
  for (int j = 0; j < 32; j += 8)
    tile[ty + j][tx] = W[(size_t)(k0 + ty + j) * N + n0 + tx];
  __syncthreads();
#pragma unroll
  for (int j = 0; j < 32; j += 8) {
    int n = n0 + ty + j;
    int k = k0 + tx;
    __half h = __float2half_rn(tile[tx][ty + j]);
    __half* row = Wt + (size_t)n * KBIG;
    row[k]          = h;
    row[DMODEL + k] = h;
  }
}

// ---------------------------------------------------------------------------
// Pipelined fp16 GEMM: C[4096, N] = A[4096, KBIG] @ Bt[N, KBIG]^T
// Block 128x128, BK=64, 3-stage cp.async, 128 threads = 4 warps (2M x 2N),
// warp tile 64x64.
// MODE 0: merged QKV epilogue (rope etc.)   MODE 3: out proj (fp32)
// ---------------------------------------------------------------------------
#define BK      64
#define STRIDE  72
#define STAGE_H (128 * STRIDE)
#define NITERS  (KBIG / BK)   // 64

template <int MODE>
__global__ __launch_bounds__(128) void gemm_f16_kernel(
    const __half* __restrict__ A, const __half* __restrict__ Bt,
    float* __restrict__ out) {
  extern __shared__ __align__(16) __half smem[];
  __half* As = smem;
  __half* Bs = smem + 3 * STAGE_H;

  const int tid  = threadIdx.x;
  const int wid  = tid >> 5;
  const int lane = tid & 31;
  const int wm   = wid >> 1;   // 0..1
  const int wn   = wid & 1;    // 0..1
  const int g    = lane >> 2;
  const int q4   = lane & 3;
  const int m0   = blockIdx.y * 128;
  const int n0   = blockIdx.x * 128;

  const uint32_t as_base = (uint32_t)__cvta_generic_to_shared(As);
  const uint32_t bs_base = (uint32_t)__cvta_generic_to_shared(Bs);

  const int crow = tid >> 3;   // 0..15
  const int cseg = tid & 7;

  const uint32_t a_off =
      (uint32_t)((wm * 64 + (lane & 15)) * STRIDE + (lane >> 4) * 8) * 2;
  const uint32_t b_off =
      (uint32_t)((wn * 64 + (lane & 7) + ((lane & 16) >> 1)) * STRIDE +
                 (lane & 8)) * 2;

  float c[4][8][4];
#pragma unroll
  for (int mt = 0; mt < 4; mt++)
#pragma unroll
    for (int nt = 0; nt < 8; nt++)
#pragma unroll
      for (int j = 0; j < 4; j++) c[mt][nt][j] = 0.f;

  auto load_stage = [&](int stg, int k0) {
    uint32_t abase = as_base + stg * STAGE_H * 2;
    uint32_t bbase = bs_base + stg * STAGE_H * 2;
#pragma unroll
    for (int j = 0; j < 8; j++) {
      int row = j * 16 + crow;
      uint32_t so = (uint32_t)(row * STRIDE + cseg * 8) * 2;
      CP_ASYNC16(abase + so, A + (size_t)(m0 + row) * KBIG + k0 + cseg * 8);
      CP_ASYNC16(bbase + so, Bt + (size_t)(n0 + row) * KBIG + k0 + cseg * 8);
    }
  };

  load_stage(0, 0);
  CP_COMMIT();
  load_stage(1, BK);
  CP_COMMIT();

  for (int it = 0; it < NITERS; it++) {
    CP_WAIT(1);
    __syncthreads();
    if (it + 2 < NITERS) load_stage((it + 2) % 3, (it + 2) * BK);
    CP_COMMIT();

    const int stg = it % 3;
    const uint32_t ab = as_base + stg * STAGE_H * 2 + a_off;
    const uint32_t bb = bs_base + stg * STAGE_H * 2 + b_off;
#pragma unroll
    for (int kt = 0; kt < 4; kt++) {
      const uint32_t ko = kt * 32;
      uint32_t a[4][4];
#pragma unroll
      for (int mt = 0; mt < 4; mt++)
        LDSM_X4(a[mt][0], a[mt][1], a[mt][2], a[mt][3],
                ab + (uint32_t)(mt * 16 * STRIDE * 2) + ko);
#pragma unroll
      for (int p = 0; p < 4; p++) {
        uint32_t b[4];
        LDSM_X4(b[0], b[1], b[2], b[3],
                bb + (uint32_t)(p * 16 * STRIDE * 2) + ko);
#pragma unroll
        for (int mt = 0; mt < 4; mt++) {
          MMA_16816(c[mt][2 * p],     a[mt], b[0], b[1]);
          MMA_16816(c[mt][2 * p + 1], a[mt], b[2], b[3]);
        }
      }
    }
  }

  const float qscale = 0.08838834764831845f;  // 1/sqrt(128)
#pragma unroll
  for (int mt = 0; mt < 4; mt++) {
#pragma unroll
    for (int nt = 0; nt < 8; nt++) {
      int col = n0 + wn * 64 + nt * 8 + q4 * 2;
      int row = m0 + wm * 64 + mt * 16 + g;
      if (MODE == 3) {
        *(float2*)&out[(size_t)row * DMODEL + col] =
            make_float2(c[mt][nt][0], c[mt][nt][1]);
        *(float2*)&out[(size_t)(row + 8) * DMODEL + col] =
            make_float2(c[mt][nt][2], c[mt][nt][3]);
      } else {
#pragma unroll
        for (int hh = 0; hh < 2; hh++) {
          int r = row + hh * 8;
          int b = r >> 11;
          int s = r & 2047;
          float v0 = c[mt][nt][hh * 2];
          float v1 = c[mt][nt][hh * 2 + 1];
          __half* dst;
          if (col < NH * HD) {            // Q: rope + scale
            int head = col >> 7, d = col & 127;
            int i    = d >> 1;
            float cs = g_cos[s * 64 + i], sn = g_sin[s * 64 + i];
            float r0 = v0 * cs - v1 * sn, r1 = v0 * sn + v1 * cs;
            v0 = r0 * qscale; v1 = r1 * qscale;
            dst = &g_q[(((size_t)(b * NH + head)) * SEQ + s) * HD + d];
          } else if (col < NH * HD + NKV * HD) {  // K: rope
            int kc = col - NH * HD;
            int head = kc >> 7, d = kc & 127;
            int i    = d >> 1;
            float cs = g_cos[s * 64 + i], sn = g_sin[s * 64 + i];
            float r0 = v0 * cs - v1 * sn, r1 = v0 * sn + v1 * cs;
            v0 = r0; v1 = r1;
            dst = &g_k[(((size_t)(b * NKV + head)) * SEQ + s) * HD + d];
          } else {                        // V
            int vc = col - NH * HD - NKV * HD;
            int head = vc >> 7, d = vc & 127;
            dst = &g_v[(((size_t)(b * NKV + head)) * SEQ + s) * HD + d];
          }
          *(__half2*)dst = __floats2half2_rn(v0, v1);
        }
      }
    }
  }
}

// ---------------------------------------------------------------------------
// Flash attention: block = (128 Q rows, head, batch), 256 threads.
// Double-buffered cp.async K/V chunks of 64 rows (FULL 128-half rows:
// crow=tid>>4, cseg=tid&15 — the round-6 bug was covering only half the row).
// ---------------------------------------------------------------------------
#define AS_ROW 136                 // halves per smem row
#define ABUF_H (128 * AS_ROW)      // halves per buffer (K rows 0-63, V 64-127)

__global__ __launch_bounds__(256) void attn_kernel(const int* __restrict__ causal_flag) {
  extern __shared__ __align__(16) __half S[];  // [2][128][AS_ROW]

  const int tid  = threadIdx.x;
  const int wid  = tid >> 5;
  const int lane = tid & 31;
  const int g    = lane >> 2;
  const int q4   = lane & 3;
  const int qtile = blockIdx.x;
  const int h     = blockIdx.y;
  const int b     = blockIdx.z;
  const int kv    = h >> 1;
  const int qbase = qtile * 128;
  const int causal = *causal_flag;

  const uint32_t s_base = (uint32_t)__cvta_generic_to_shared(S);
  const uint32_t q_a = s_base +
      (uint32_t)((wid * 16 + (lane & 15)) * AS_ROW + (lane >> 4) * 8) * 2;
  const uint32_t k_b = s_base +
      (uint32_t)(((lane & 7) + ((lane & 16) >> 1)) * AS_ROW + (lane & 8)) * 2;
  const uint32_t v_b = s_base +
      (uint32_t)((64 + (lane & 15)) * AS_ROW + (lane >> 4) * 8) * 2;

  // Stage Q tile (128 x 128) into buffer 0 and extract A fragments
  const __half* qp = g_q + (((size_t)(b * NH + h)) * SEQ + qbase) * HD;
#pragma unroll
  for (int j = 0; j < 8; j++) {
    int i   = j * 256 + tid;
    int row = i >> 4;
    int seg = i & 15;
    *(uint4*)&S[row * AS_ROW + seg * 8] = *(const uint4*)(qp + row * HD + seg * 8);
  }
  __syncthreads();
  uint32_t qa[8][4];
#pragma unroll
  for (int kt = 0; kt < 8; kt++)
    LDSM_X4(qa[kt][0], qa[kt][1], qa[kt][2], qa[kt][3], q_a + kt * 32);
  __syncthreads();  // all extractions done before cp.async overwrites buffer 0

  float o[16][4];
#pragma unroll
  for (int i = 0; i < 16; i++)
#pragma unroll
    for (int j = 0; j < 4; j++) o[i][j] = 0.f;
  float m0 = -1e30f, m1 = -1e30f, l0 = 0.f, l1 = 0.f;

  const int jend = causal ? (qbase + 128) : SEQ;
  const int nchunks = jend >> 6;
  const __half* kbp = g_k + ((size_t)(b * NKV + kv)) * SEQ * HD;
  const __half* vbp = g_v + ((size_t)(b * NKV + kv)) * SEQ * HD;
  const int row0 = qbase + wid * 16 + g;
  const int row1 = row0 + 8;

  const int crow = tid >> 4;   // 0..15
  const int cseg = tid & 15;   // 0..15 -> cseg*8 covers all 128 halves

  auto load_chunk = [&](int stg, int j0) {
    uint32_t base = s_base + (uint32_t)stg * ABUF_H * 2;
#pragma unroll
    for (int j = 0; j < 4; j++) {
      int row = j * 16 + crow;   // 0..63
      uint32_t so = (uint32_t)(row * AS_ROW + cseg * 8) * 2;
      CP_ASYNC16(base + so, kbp + (size_t)(j0 + row) * HD + cseg * 8);
      CP_ASYNC16(base + (uint32_t)(64 * AS_ROW * 2) + so,
                 vbp + (size_t)(j0 + row) * HD + cseg * 8);
    }
  };

  load_chunk(0, 0);
  CP_COMMIT();

  for (int ci = 0; ci < nchunks; ci++) {
    const int j0 = ci * 64;
    CP_WAIT(0);
    __syncthreads();
    if (ci + 1 < nchunks) load_chunk((ci + 1) & 1, j0 + 64);
    CP_COMMIT();

    const uint32_t soff = (uint32_t)(ci & 1) * ABUF_H * 2;

    // S = Q @ K^T : per warp 16 x 64
    float sc[8][4];
#pragma unroll
    for (int i = 0; i < 8; i++)
#pragma unroll
      for (int j = 0; j < 4; j++) sc[i][j] = 0.f;
#pragma unroll
    for (int kt = 0; kt < 8; kt++) {
#pragma unroll
      for (int p = 0; p < 4; p++) {
        uint32_t bf[4];
        LDSM_X4(bf[0], bf[1], bf[2], bf[3],
                k_b + soff + (uint32_t)(p * 16 * AS_ROW * 2) + kt * 32);
        MMA_16816(sc[2 * p],     qa[kt], bf[0], bf[1]);
        MMA_16816(sc[2 * p + 1], qa[kt], bf[2], bf[3]);
      }
    }

    if (causal && j0 + 64 > qbase) {
#pragma unroll
      for (int nt = 0; nt < 8; nt++) {
        int col = j0 + nt * 8 + q4 * 2;
        if (col     > row0) sc[nt][0] = -1e30f;
        if (col + 1 > row0) sc[nt][1] = -1e30f;
        if (col     > row1) sc[nt][2] = -1e30f;
        if (col + 1 > row1) sc[nt][3] = -1e30f;
      }
    }

    float r0 = -1e30f, r1 = -1e30f;
#pragma unroll
    for (int nt = 0; nt < 8; nt++) {
      r0 = fmaxf(r0, fmaxf(sc[nt][0], sc[nt][1]));
      r1 = fmaxf(r1, fmaxf(sc[nt][2], sc[nt][3]));
    }
    r0 = fmaxf(r0, __shfl_xor_sync(0xffffffffu, r0, 1));
    r0 = fmaxf(r0, __shfl_xor_sync(0xffffffffu, r0, 2));
    r1 = fmaxf(r1, __shfl_xor_sync(0xffffffffu, r1, 1));
    r1 = fmaxf(r1, __shfl_xor_sync(0xffffffffu, r1, 2));
    float mn0 = fmaxf(m0, r0), mn1 = fmaxf(m1, r1);
    float sf0 = __expf(m0 - mn0), sf1 = __expf(m1 - mn1);
    m0 = mn0; m1 = mn1;
    float s0 = 0.f, s1 = 0.f;
#pragma unroll
    for (int nt = 0; nt < 8; nt++) {
      sc[nt][0] = __expf(sc[nt][0] - mn0);
      sc[nt][1] = __expf(sc[nt][1] - mn0);
      sc[nt][2] = __expf(sc[nt][2] - mn1);
      sc[nt][3] = __expf(sc[nt][3] - mn1);
      s0 += sc[nt][0] + sc[nt][1];
      s1 += sc[nt][2] + sc[nt][3];
    }
    s0 += __shfl_xor_sync(0xffffffffu, s0, 1);
    s0 += __shfl_xor_sync(0xffffffffu, s0, 2);
    s1 += __shfl_xor_sync(0xffffffffu, s1, 1);
    s1 += __shfl_xor_sync(0xffffffffu, s1, 2);
    l0 = l0 * sf0 + s0;
    l1 = l1 * sf1 + s1;
#pragma unroll
    for (int i = 0; i < 16; i++) {
      o[i][0] *= sf0; o[i][1] *= sf0;
      o[i][2] *= sf1; o[i][3] *= sf1;
    }

    uint32_t pa[4][4];
#pragma unroll
    for (int kt = 0; kt < 4; kt++) {
      pa[kt][0] = pack_half2(sc[2 * kt][0], sc[2 * kt][1]);
      pa[kt][1] = pack_half2(sc[2 * kt][2], sc[2 * kt][3]);
      pa[kt][2] = pack_half2(sc[2 * kt + 1][0], sc[2 * kt + 1][1]);
      pa[kt][3] = pack_half2(sc[2 * kt + 1][2], sc[2 * kt + 1][3]);
    }

    // O += P @ V : V B-fragments via ldmatrix.trans from natural [s][d]
#pragma unroll
    for (int kt = 0; kt < 4; kt++) {
#pragma unroll
      for (int pb = 0; pb < 8; pb++) {
        uint32_t bf[4];
        LDSM_X4_T(bf[0], bf[1], bf[2], bf[3],
                  v_b + soff + (uint32_t)(kt * 16 * AS_ROW * 2) + pb * 32);
        MMA_16816(o[2 * pb],     pa[kt], bf[0], bf[1]);
        MMA_16816(o[2 * pb + 1], pa[kt], bf[2], bf[3]);
      }
    }
  }

  // Normalize, split hi/lo, store into g_obig = [oh | ol]
  float inv0 = 1.f / l0, inv1 = 1.f / l1;
#pragma unroll
  for (int nt = 0; nt < 16; nt++) {
    int d = nt * 8 + q4 * 2;
#pragma unroll
    for (int hh = 0; hh < 2; hh++) {
      int r = (hh == 0) ? row0 : row1;
      float v0 = o[nt][hh * 2]     * (hh == 0 ? inv0 : inv1);
      float v1 = o[nt][hh * 2 + 1] * (hh == 0 ? inv0 : inv1);
      __half h0 = __float2half_rn(v0);
      __half h1 = __float2half_rn(v1);
      __half e0 = __float2half_rn(v0 - __half2float(h0));
      __half e1 = __float2half_rn(v1 - __half2float(h1));
      __half* base = g_obig + (size_t)(b * SEQ + r) * KBIG + h * HD + d;
      *(__half2*)(base)          = __halves2half2(h0, h1);
      *(__half2*)(base + DMODEL) = __halves2half2(e0, e1);
    }
  }
}

// ---------------------------------------------------------------------------
// Launch
// ---------------------------------------------------------------------------
extern "C" void kernel_launch(void* const* d_in, const int* in_sizes, int n_in,
                              void* d_out, int out_size) {
  const float* x  = (const float*)d_in[0];
  const float* Wq = (const float*)d_in[1];
  const float* Wk = (const float*)d_in[2];
  const float* Wv = (const float*)d_in[3];
  const float* Wo = (const float*)d_in[4];
  const int* is_causal = (const int*)d_in[5];
  float* out = (float*)d_out;

  __half *xbig, *obig, *wt, *wot;
  cudaGetSymbolAddress((void**)&xbig, g_xbig);
  cudaGetSymbolAddress((void**)&obig, g_obig);
  cudaGetSymbolAddress((void**)&wt,  g_wt);
  cudaGetSymbolAddress((void**)&wot, g_wot);

  const int gemm_smem = 6 * STAGE_H * 2;   // 110592
  const int attn_smem = 2 * ABUF_H * 2;    // 69632
  cudaFuncSetAttribute(gemm_f16_kernel<0>,
                       cudaFuncAttributeMaxDynamicSharedMemorySize, gemm_smem);
  cudaFuncSetAttribute(gemm_f16_kernel<3>,
                       cudaFuncAttributeMaxDynamicSharedMemorySize, gemm_smem);
  cudaFuncSetAttribute(attn_kernel,
                       cudaFuncAttributeMaxDynamicSharedMemorySize, attn_smem);

  rope_init_kernel<<<(SEQ * 64 + 255) / 256, 256>>>();
  split_x_kernel<<<(MROWS * DMODEL) / 256, 256>>>(x);
  tsplit_w_kernel<<<dim3((NH * HD) / 32, DMODEL / 32), dim3(32, 8)>>>(
      Wq, wt, NH * HD);
  tsplit_w_kernel<<<dim3((NKV * HD) / 32, DMODEL / 32), dim3(32, 8)>>>(
      Wk, wt + (size_t)(NH * HD) * KBIG, NKV * HD);
  tsplit_w_kernel<<<dim3((NKV * HD) / 32, DMODEL / 32), dim3(32, 8)>>>(
      Wv, wt + (size_t)(NH * HD + NKV * HD) * KBIG, NKV * HD);
  tsplit_w_kernel<<<dim3(DMODEL / 32, DMODEL / 32), dim3(32, 8)>>>(Wo, wot, DMODEL);

  gemm_f16_kernel<0><<<dim3(NQKV / 128, MROWS / 128), 128, gemm_smem>>>(
      xbig, wt, nullptr);

  attn_kernel<<<dim3(SEQ / 128, NH, BATCH), 256, attn_smem>>>(is_causal);

  gemm_f16_kernel<3><<<dim3(DMODEL / 128, MROWS / 128), 128, gemm_smem>>>(
      obig, wot, out);
}

// round 11
// speedup vs baseline: 5.4916x; 1.5551x over previous
#include <cuda_runtime.h>
#include <cuda_fp16.h>
#include <math.h>
#include <stdint.h>

#define BATCH  2
#define SEQ    2048
#define DMODEL 2048
#define NH     16
#define NKV    8
#define HD     128
#define KBIG   DMODEL         // 2048: plain fp16 operands (A and W quantized)
#define MROWS  (BATCH * SEQ)  // 4096
#define NQKV   (NH * HD + 2 * NKV * HD)  // 4096 combined QKV columns

// ---------------------------------------------------------------------------
// Scratch (device globals; no allocation allowed)
// ---------------------------------------------------------------------------
__device__ __half g_xh [(size_t)MROWS * DMODEL];      // x quantized to fp16
__device__ __half g_oh [(size_t)MROWS * DMODEL];      // attn out fp16 [m][h*HD+d]
__device__ __half g_wt [(size_t)NQKV * DMODEL];       // [n][k] fp16 (Q|K|V)
__device__ __half g_wot[(size_t)DMODEL * DMODEL];     // [n][k] fp16
__device__ __half g_q[(size_t)BATCH * NH  * SEQ * HD];
__device__ __half g_k[(size_t)BATCH * NKV * SEQ * HD];
__device__ __half g_v[(size_t)BATCH * NKV * SEQ * HD];
__device__ float  g_cos[SEQ * (HD / 2)];
__device__ float  g_sin[SEQ * (HD / 2)];

// ---------------------------------------------------------------------------
// Helpers
// ---------------------------------------------------------------------------
__device__ __forceinline__ uint32_t pack_half2(float a, float b) {
  __half2 h = __floats2half2_rn(a, b);
  return *reinterpret_cast<uint32_t*>(&h);
}

#define MMA_16816(C, A, B0, B1)                                              \
  asm volatile(                                                              \
      "mma.sync.aligned.m16n8k16.row.col.f32.f16.f16.f32 "                   \
      "{%0,%1,%2,%3}, {%4,%5,%6,%7}, {%8,%9}, {%0,%1,%2,%3};\n"              \
      : "+f"((C)[0]), "+f"((C)[1]), "+f"((C)[2]), "+f"((C)[3])               \
      : "r"((A)[0]), "r"((A)[1]), "r"((A)[2]), "r"((A)[3]),                  \
        "r"(B0), "r"(B1))

#define LDSM_X4(R0, R1, R2, R3, ADDR)                                        \
  asm volatile(                                                              \
      "ldmatrix.sync.aligned.m8n8.x4.shared.b16 {%0,%1,%2,%3}, [%4];\n"      \
      : "=r"(R0), "=r"(R1), "=r"(R2), "=r"(R3) : "r"(ADDR))

#define LDSM_X4_T(R0, R1, R2, R3, ADDR)                                      \
  asm volatile(                                                              \
      "ldmatrix.sync.aligned.m8n8.x4.trans.shared.b16 {%0,%1,%2,%3}, [%4];\n"\
      : "=r"(R0), "=r"(R1), "=r"(R2), "=r"(R3) : "r"(ADDR))

#define CP_ASYNC16(DST, SRC)                                                 \
  asm volatile("cp.async.cg.shared.global [%0], [%1], 16;\n" ::              \
                   "r"(DST), "l"(SRC))
#define CP_COMMIT() asm volatile("cp.async.commit_group;\n")
#define CP_WAIT(N)  asm volatile("cp.async.wait_group %0;\n" ::"n"(N))

// ---------------------------------------------------------------------------
// Precompute kernels
// ---------------------------------------------------------------------------
__global__ void rope_init_kernel() {
  int idx = blockIdx.x * blockDim.x + threadIdx.x;
  if (idx < SEQ * (HD / 2)) {
    int s = idx >> 6;
    int i = idx & 63;
    float inv = (float)pow(10000.0, -(double)(2 * i) / (double)HD);
    float a = (float)s * inv;
    g_cos[idx] = cosf(a);
    g_sin[idx] = sinf(a);
  }
}

// x fp32 -> fp16
__global__ void conv_x_kernel(const float* __restrict__ x) {
  int idx = blockIdx.x * blockDim.x + threadIdx.x;
  if (idx < MROWS * DMODEL) {
    float4 v = *(const float4*)(x + (size_t)idx * 4);
    __half2 a = __floats2half2_rn(v.x, v.y);
    __half2 b = __floats2half2_rn(v.z, v.w);
    *(uint2*)(g_xh + (size_t)idx * 4) =
        make_uint2(*(uint32_t*)&a, *(uint32_t*)&b);
  }
}

// W[k][n] fp32 -> Wt[n][k] fp16 (tiled transpose)
__global__ void tw_kernel(const float* __restrict__ W,
                          __half* __restrict__ Wt, int N) {
  __shared__ float tile[32][33];
  const int n0 = blockIdx.x * 32;
  const int k0 = blockIdx.y * 32;
  const int tx = threadIdx.x;
  const int ty = threadIdx.y;
#pragma unroll
  for (int j = 0; j < 32; j += 8)
    tile[ty + j][tx] = W[(size_t)(k0 + ty + j) * N + n0 + tx];
  __syncthreads();
#pragma unroll
  for (int j = 0; j < 32; j += 8) {
    int n = n0 + ty + j;
    int k = k0 + tx;
    Wt[(size_t)n * DMODEL + k] = __float2half_rn(tile[tx][ty + j]);
  }
}

// ---------------------------------------------------------------------------
// Pipelined fp16 GEMM: C[4096, N] = A[4096, 2048] @ Bt[N, 2048]^T
// Block 128x128, BK=64, 3-stage cp.async, 128 threads = 4 warps (2M x 2N),
// warp tile 64x64.
// MODE 0: merged QKV epilogue (rope etc.)   MODE 3: out proj (fp32)
// ---------------------------------------------------------------------------
#define BK      64
#define STRIDE  72
#define STAGE_H (128 * STRIDE)
#define NITERS  (KBIG / BK)   // 32

template <int MODE>
__global__ __launch_bounds__(128) void gemm_f16_kernel(
    const __half* __restrict__ A, const __half* __restrict__ Bt,
    float* __restrict__ out) {
  extern __shared__ __align__(16) __half smem[];
  __half* As = smem;
  __half* Bs = smem + 3 * STAGE_H;

  const int tid  = threadIdx.x;
  const int wid  = tid >> 5;
  const int lane = tid & 31;
  const int wm   = wid >> 1;   // 0..1
  const int wn   = wid & 1;    // 0..1
  const int g    = lane >> 2;
  const int q4   = lane & 3;
  const int m0   = blockIdx.y * 128;
  const int n0   = blockIdx.x * 128;

  const uint32_t as_base = (uint32_t)__cvta_generic_to_shared(As);
  const uint32_t bs_base = (uint32_t)__cvta_generic_to_shared(Bs);

  const int crow = tid >> 3;   // 0..15
  const int cseg = tid & 7;

  const uint32_t a_off =
      (uint32_t)((wm * 64 + (lane & 15)) * STRIDE + (lane >> 4) * 8) * 2;
  const uint32_t b_off =
      (uint32_t)((wn * 64 + (lane & 7) + ((lane & 16) >> 1)) * STRIDE +
                 (lane & 8)) * 2;

  float c[4][8][4];
#pragma unroll
  for (int mt = 0; mt < 4; mt++)
#pragma unroll
    for (int nt = 0; nt < 8; nt++)
#pragma unroll
      for (int j = 0; j < 4; j++) c[mt][nt][j] = 0.f;

  auto load_stage = [&](int stg, int k0) {
    uint32_t abase = as_base + stg * STAGE_H * 2;
    uint32_t bbase = bs_base + stg * STAGE_H * 2;
#pragma unroll
    for (int j = 0; j < 8; j++) {
      int row = j * 16 + crow;
      uint32_t so = (uint32_t)(row * STRIDE + cseg * 8) * 2;
      CP_ASYNC16(abase + so, A + (size_t)(m0 + row) * KBIG + k0 + cseg * 8);
      CP_ASYNC16(bbase + so, Bt + (size_t)(n0 + row) * KBIG + k0 + cseg * 8);
    }
  };

  load_stage(0, 0);
  CP_COMMIT();
  load_stage(1, BK);
  CP_COMMIT();

  for (int it = 0; it < NITERS; it++) {
    CP_WAIT(1);
    __syncthreads();
    if (it + 2 < NITERS) load_stage((it + 2) % 3, (it + 2) * BK);
    CP_COMMIT();

    const int stg = it % 3;
    const uint32_t ab = as_base + stg * STAGE_H * 2 + a_off;
    const uint32_t bb = bs_base + stg * STAGE_H * 2 + b_off;
#pragma unroll
    for (int kt = 0; kt < 4; kt++) {
      const uint32_t ko = kt * 32;
      uint32_t a[4][4];
#pragma unroll
      for (int mt = 0; mt < 4; mt++)
        LDSM_X4(a[mt][0], a[mt][1], a[mt][2], a[mt][3],
                ab + (uint32_t)(mt * 16 * STRIDE * 2) + ko);
#pragma unroll
      for (int p = 0; p < 4; p++) {
        uint32_t b[4];
        LDSM_X4(b[0], b[1], b[2], b[3],
                bb + (uint32_t)(p * 16 * STRIDE * 2) + ko);
#pragma unroll
        for (int mt = 0; mt < 4; mt++) {
          MMA_16816(c[mt][2 * p],     a[mt], b[0], b[1]);
          MMA_16816(c[mt][2 * p + 1], a[mt], b[2], b[3]);
        }
      }
    }
  }

  const float qscale = 0.08838834764831845f;  // 1/sqrt(128)
#pragma unroll
  for (int mt = 0; mt < 4; mt++) {
#pragma unroll
    for (int nt = 0; nt < 8; nt++) {
      int col = n0 + wn * 64 + nt * 8 + q4 * 2;
      int row = m0 + wm * 64 + mt * 16 + g;
      if (MODE == 3) {
        *(float2*)&out[(size_t)row * DMODEL + col] =
            make_float2(c[mt][nt][0], c[mt][nt][1]);
        *(float2*)&out[(size_t)(row + 8) * DMODEL + col] =
            make_float2(c[mt][nt][2], c[mt][nt][3]);
      } else {
#pragma unroll
        for (int hh = 0; hh < 2; hh++) {
          int r = row + hh * 8;
          int b = r >> 11;
          int s = r & 2047;
          float v0 = c[mt][nt][hh * 2];
          float v1 = c[mt][nt][hh * 2 + 1];
          __half* dst;
          if (col < NH * HD) {            // Q: rope + scale
            int head = col >> 7, d = col & 127;
            int i    = d >> 1;
            float cs = g_cos[s * 64 + i], sn = g_sin[s * 64 + i];
            float r0 = v0 * cs - v1 * sn, r1 = v0 * sn + v1 * cs;
            v0 = r0 * qscale; v1 = r1 * qscale;
            dst = &g_q[(((size_t)(b * NH + head)) * SEQ + s) * HD + d];
          } else if (col < NH * HD + NKV * HD) {  // K: rope
            int kc = col - NH * HD;
            int head = kc >> 7, d = kc & 127;
            int i    = d >> 1;
            float cs = g_cos[s * 64 + i], sn = g_sin[s * 64 + i];
            float r0 = v0 * cs - v1 * sn, r1 = v0 * sn + v1 * cs;
            v0 = r0; v1 = r1;
            dst = &g_k[(((size_t)(b * NKV + head)) * SEQ + s) * HD + d];
          } else {                        // V
            int vc = col - NH * HD - NKV * HD;
            int head = vc >> 7, d = vc & 127;
            dst = &g_v[(((size_t)(b * NKV + head)) * SEQ + s) * HD + d];
          }
          *(__half2*)dst = __floats2half2_rn(v0, v1);
        }
      }
    }
  }
}

// ---------------------------------------------------------------------------
// Flash attention: block = (128 Q rows, head, batch), 256 threads.
// Double-buffered cp.async K/V chunks of 64 rows.
// ---------------------------------------------------------------------------
#define AS_ROW 136                 // halves per smem row
#define ABUF_H (128 * AS_ROW)      // halves per buffer (K rows 0-63, V 64-127)

__global__ __launch_bounds__(256) void attn_kernel(const int* __restrict__ causal_flag) {
  extern __shared__ __align__(16) __half S[];  // [2][128][AS_ROW]

  const int tid  = threadIdx.x;
  const int wid  = tid >> 5;
  const int lane = tid & 31;
  const int g    = lane >> 2;
  const int q4   = lane & 3;
  const int qtile = blockIdx.x;
  const int h     = blockIdx.y;
  const int b     = blockIdx.z;
  const int kv    = h >> 1;
  const int qbase = qtile * 128;
  const int causal = *causal_flag;

  const uint32_t s_base = (uint32_t)__cvta_generic_to_shared(S);
  const uint32_t q_a = s_base +
      (uint32_t)((wid * 16 + (lane & 15)) * AS_ROW + (lane >> 4) * 8) * 2;
  const uint32_t k_b = s_base +
      (uint32_t)(((lane & 7) + ((lane & 16) >> 1)) * AS_ROW + (lane & 8)) * 2;
  const uint32_t v_b = s_base +
      (uint32_t)((64 + (lane & 15)) * AS_ROW + (lane >> 4) * 8) * 2;

  // Stage Q tile (128 x 128) into buffer 0 and extract A fragments
  const __half* qp = g_q + (((size_t)(b * NH + h)) * SEQ + qbase) * HD;
#pragma unroll
  for (int j = 0; j < 8; j++) {
    int i   = j * 256 + tid;
    int row = i >> 4;
    int seg = i & 15;
    *(uint4*)&S[row * AS_ROW + seg * 8] = *(const uint4*)(qp + row * HD + seg * 8);
  }
  __syncthreads();
  uint32_t qa[8][4];
#pragma unroll
  for (int kt = 0; kt < 8; kt++)
    LDSM_X4(qa[kt][0], qa[kt][1], qa[kt][2], qa[kt][3], q_a + kt * 32);
  __syncthreads();  // all extractions done before cp.async overwrites buffer 0

  float o[16][4];
#pragma unroll
  for (int i = 0; i < 16; i++)
#pragma unroll
    for (int j = 0; j < 4; j++) o[i][j] = 0.f;
  float m0 = -1e30f, m1 = -1e30f, l0 = 0.f, l1 = 0.f;

  const int jend = causal ? (qbase + 128) : SEQ;
  const int nchunks = jend >> 6;
  const __half* kbp = g_k + ((size_t)(b * NKV + kv)) * SEQ * HD;
  const __half* vbp = g_v + ((size_t)(b * NKV + kv)) * SEQ * HD;
  const int row0 = qbase + wid * 16 + g;
  const int row1 = row0 + 8;

  const int crow = tid >> 4;   // 0..15
  const int cseg = tid & 15;   // 0..15 -> cseg*8 covers all 128 halves

  auto load_chunk = [&](int stg, int j0) {
    uint32_t base = s_base + (uint32_t)stg * ABUF_H * 2;
#pragma unroll
    for (int j = 0; j < 4; j++) {
      int row = j * 16 + crow;   // 0..63
      uint32_t so = (uint32_t)(row * AS_ROW + cseg * 8) * 2;
      CP_ASYNC16(base + so, kbp + (size_t)(j0 + row) * HD + cseg * 8);
      CP_ASYNC16(base + (uint32_t)(64 * AS_ROW * 2) + so,
                 vbp + (size_t)(j0 + row) * HD + cseg * 8);
    }
  };

  load_chunk(0, 0);
  CP_COMMIT();

  for (int ci = 0; ci < nchunks; ci++) {
    const int j0 = ci * 64;
    CP_WAIT(0);
    __syncthreads();
    if (ci + 1 < nchunks) load_chunk((ci + 1) & 1, j0 + 64);
    CP_COMMIT();

    const uint32_t soff = (uint32_t)(ci & 1) * ABUF_H * 2;

    // S = Q @ K^T : per warp 16 x 64
    float sc[8][4];
#pragma unroll
    for (int i = 0; i < 8; i++)
#pragma unroll
      for (int j = 0; j < 4; j++) sc[i][j] = 0.f;
#pragma unroll
    for (int kt = 0; kt < 8; kt++) {
#pragma unroll
      for (int p = 0; p < 4; p++) {
        uint32_t bf[4];
        LDSM_X4(bf[0], bf[1], bf[2], bf[3],
                k_b + soff + (uint32_t)(p * 16 * AS_ROW * 2) + kt * 32);
        MMA_16816(sc[2 * p],     qa[kt], bf[0], bf[1]);
        MMA_16816(sc[2 * p + 1], qa[kt], bf[2], bf[3]);
      }
    }

    if (causal && j0 + 64 > qbase) {
#pragma unroll
      for (int nt = 0; nt < 8; nt++) {
        int col = j0 + nt * 8 + q4 * 2;
        if (col     > row0) sc[nt][0] = -1e30f;
        if (col + 1 > row0) sc[nt][1] = -1e30f;
        if (col     > row1) sc[nt][2] = -1e30f;
        if (col + 1 > row1) sc[nt][3] = -1e30f;
      }
    }

    float r0 = -1e30f, r1 = -1e30f;
#pragma unroll
    for (int nt = 0; nt < 8; nt++) {
      r0 = fmaxf(r0, fmaxf(sc[nt][0], sc[nt][1]));
      r1 = fmaxf(r1, fmaxf(sc[nt][2], sc[nt][3]));
    }
    r0 = fmaxf(r0, __shfl_xor_sync(0xffffffffu, r0, 1));
    r0 = fmaxf(r0, __shfl_xor_sync(0xffffffffu, r0, 2));
    r1 = fmaxf(r1, __shfl_xor_sync(0xffffffffu, r1, 1));
    r1 = fmaxf(r1, __shfl_xor_sync(0xffffffffu, r1, 2));
    float mn0 = fmaxf(m0, r0), mn1 = fmaxf(m1, r1);
    float sf0 = __expf(m0 - mn0), sf1 = __expf(m1 - mn1);
    m0 = mn0; m1 = mn1;
    float s0 = 0.f, s1 = 0.f;
#pragma unroll
    for (int nt = 0; nt < 8; nt++) {
      sc[nt][0] = __expf(sc[nt][0] - mn0);
      sc[nt][1] = __expf(sc[nt][1] - mn0);
      sc[nt][2] = __expf(sc[nt][2] - mn1);
      sc[nt][3] = __expf(sc[nt][3] - mn1);
      s0 += sc[nt][0] + sc[nt][1];
      s1 += sc[nt][2] + sc[nt][3];
    }
    s0 += __shfl_xor_sync(0xffffffffu, s0, 1);
    s0 += __shfl_xor_sync(0xffffffffu, s0, 2);
    s1 += __shfl_xor_sync(0xffffffffu, s1, 1);
    s1 += __shfl_xor_sync(0xffffffffu, s1, 2);
    l0 = l0 * sf0 + s0;
    l1 = l1 * sf1 + s1;
#pragma unroll
    for (int i = 0; i < 16; i++) {
      o[i][0] *= sf0; o[i][1] *= sf0;
      o[i][2] *= sf1; o[i][3] *= sf1;
    }

    uint32_t pa[4][4];
#pragma unroll
    for (int kt = 0; kt < 4; kt++) {
      pa[kt][0] = pack_half2(sc[2 * kt][0], sc[2 * kt][1]);
      pa[kt][1] = pack_half2(sc[2 * kt][2], sc[2 * kt][3]);
      pa[kt][2] = pack_half2(sc[2 * kt + 1][0], sc[2 * kt + 1][1]);
      pa[kt][3] = pack_half2(sc[2 * kt + 1][2], sc[2 * kt + 1][3]);
    }

    // O += P @ V : V B-fragments via ldmatrix.trans from natural [s][d]
#pragma unroll
    for (int kt = 0; kt < 4; kt++) {
#pragma unroll
      for (int pb = 0; pb < 8; pb++) {
        uint32_t bf[4];
        LDSM_X4_T(bf[0], bf[1], bf[2], bf[3],
                  v_b + soff + (uint32_t)(kt * 16 * AS_ROW * 2) + pb * 32);
        MMA_16816(o[2 * pb],     pa[kt], bf[0], bf[1]);
        MMA_16816(o[2 * pb + 1], pa[kt], bf[2], bf[3]);
      }
    }
  }

  // Normalize, store fp16 into g_oh[(b*S + s)][h*HD + d]
  float inv0 = 1.f / l0, inv1 = 1.f / l1;
#pragma unroll
  for (int nt = 0; nt < 16; nt++) {
    int d = nt * 8 + q4 * 2;
#pragma unroll
    for (int hh = 0; hh < 2; hh++) {
      int r = (hh == 0) ? row0 : row1;
      float v0 = o[nt][hh * 2]     * (hh == 0 ? inv0 : inv1);
      float v1 = o[nt][hh * 2 + 1] * (hh == 0 ? inv0 : inv1);
      __half* base = g_oh + (size_t)(b * SEQ + r) * DMODEL + h * HD + d;
      *(__half2*)base = __floats2half2_rn(v0, v1);
    }
  }
}

// ---------------------------------------------------------------------------
// Launch
// ---------------------------------------------------------------------------
extern "C" void kernel_launch(void* const* d_in, const int* in_sizes, int n_in,
                              void* d_out, int out_size) {
  const float* x  = (const float*)d_in[0];
  const float* Wq = (const float*)d_in[1];
  const float* Wk = (const float*)d_in[2];
  const float* Wv = (const float*)d_in[3];
  const float* Wo = (const float*)d_in[4];
  const int* is_causal = (const int*)d_in[5];
  float* out = (float*)d_out;

  __half *xh, *oh, *wt, *wot;
  cudaGetSymbolAddress((void**)&xh,  g_xh);
  cudaGetSymbolAddress((void**)&oh,  g_oh);
  cudaGetSymbolAddress((void**)&wt,  g_wt);
  cudaGetSymbolAddress((void**)&wot, g_wot);

  const int gemm_smem = 6 * STAGE_H * 2;   // 110592
  const int attn_smem = 2 * ABUF_H * 2;    // 69632
  cudaFuncSetAttribute(gemm_f16_kernel<0>,
                       cudaFuncAttributeMaxDynamicSharedMemorySize, gemm_smem);
  cudaFuncSetAttribute(gemm_f16_kernel<3>,
                       cudaFuncAttributeMaxDynamicSharedMemorySize, gemm_smem);
  cudaFuncSetAttribute(attn_kernel,
                       cudaFuncAttributeMaxDynamicSharedMemorySize, attn_smem);

  rope_init_kernel<<<(SEQ * 64 + 255) / 256, 256>>>();
  conv_x_kernel<<<(MROWS * DMODEL / 4) / 256, 256>>>(x);
  tw_kernel<<<dim3((NH * HD) / 32, DMODEL / 32), dim3(32, 8)>>>(
      Wq, wt, NH * HD);
  tw_kernel<<<dim3((NKV * HD) / 32, DMODEL / 32), dim3(32, 8)>>>(
      Wk, wt + (size_t)(NH * HD) * DMODEL, NKV * HD);
  tw_kernel<<<dim3((NKV * HD) / 32, DMODEL / 32), dim3(32, 8)>>>(
      Wv, wt + (size_t)(NH * HD + NKV * HD) * DMODEL, NKV * HD);
  tw_kernel<<<dim3(DMODEL / 32, DMODEL / 32), dim3(32, 8)>>>(Wo, wot, DMODEL);

  gemm_f16_kernel<0><<<dim3(NQKV / 128, MROWS / 128), 128, gemm_smem>>>(
      xh, wt, nullptr);

  attn_kernel<<<dim3(SEQ / 128, NH, BATCH), 256, attn_smem>>>(is_causal);

  gemm_f16_kernel<3><<<dim3(DMODEL / 128, MROWS / 128), 128, gemm_smem>>>(
      oh, wot, out);
}

// round 12
// speedup vs baseline: 5.9441x; 1.0824x over previous
#include <cuda_runtime.h>
#include <cuda_fp16.h>
#include <math.h>
#include <stdint.h>

#define BATCH  2
#define SEQ    2048
#define DMODEL 2048
#define NH     16
#define NKV    8
#define HD     128
#define KBIG   DMODEL         // 2048: plain fp16 operands (A and W quantized)
#define MROWS  (BATCH * SEQ)  // 4096
#define NQKV   (NH * HD + 2 * NKV * HD)  // 4096 combined QKV columns

// ---------------------------------------------------------------------------
// Scratch (device globals; no allocation allowed)
// ---------------------------------------------------------------------------
__device__ __half g_xh [(size_t)MROWS * DMODEL];      // x quantized to fp16
__device__ __half g_oh [(size_t)MROWS * DMODEL];      // attn out fp16 [m][h*HD+d]
__device__ __half g_wt [(size_t)NQKV * DMODEL];       // [n][k] fp16 (Q|K|V)
__device__ __half g_wot[(size_t)DMODEL * DMODEL];     // [n][k] fp16
__device__ __half g_q[(size_t)BATCH * NH  * SEQ * HD];
__device__ __half g_k[(size_t)BATCH * NKV * SEQ * HD];
__device__ __half g_v[(size_t)BATCH * NKV * SEQ * HD];
__device__ float  g_cos[SEQ * (HD / 2)];
__device__ float  g_sin[SEQ * (HD / 2)];

// ---------------------------------------------------------------------------
// Helpers
// ---------------------------------------------------------------------------
__device__ __forceinline__ uint32_t pack_half2(float a, float b) {
  __half2 h = __floats2half2_rn(a, b);
  return *reinterpret_cast<uint32_t*>(&h);
}

__device__ __forceinline__ float ex2f(float x) {
  float r;
  asm("ex2.approx.f32 %0, %1;" : "=f"(r) : "f"(x));
  return r;
}

#define MMA_16816(C, A, B0, B1)                                              \
  asm volatile(                                                              \
      "mma.sync.aligned.m16n8k16.row.col.f32.f16.f16.f32 "                   \
      "{%0,%1,%2,%3}, {%4,%5,%6,%7}, {%8,%9}, {%0,%1,%2,%3};\n"              \
      : "+f"((C)[0]), "+f"((C)[1]), "+f"((C)[2]), "+f"((C)[3])               \
      : "r"((A)[0]), "r"((A)[1]), "r"((A)[2]), "r"((A)[3]),                  \
        "r"(B0), "r"(B1))

#define LDSM_X4(R0, R1, R2, R3, ADDR)                                        \
  asm volatile(                                                              \
      "ldmatrix.sync.aligned.m8n8.x4.shared.b16 {%0,%1,%2,%3}, [%4];\n"      \
      : "=r"(R0), "=r"(R1), "=r"(R2), "=r"(R3) : "r"(ADDR))

#define LDSM_X4_T(R0, R1, R2, R3, ADDR)                                      \
  asm volatile(                                                              \
      "ldmatrix.sync.aligned.m8n8.x4.trans.shared.b16 {%0,%1,%2,%3}, [%4];\n"\
      : "=r"(R0), "=r"(R1), "=r"(R2), "=r"(R3) : "r"(ADDR))

#define LDSM_X2_T(R0, R1, ADDR)                                              \
  asm volatile(                                                              \
      "ldmatrix.sync.aligned.m8n8.x2.trans.shared.b16 {%0,%1}, [%2];\n"      \
      : "=r"(R0), "=r"(R1) : "r"(ADDR))

#define CP_ASYNC16(DST, SRC)                                                 \
  asm volatile("cp.async.cg.shared.global [%0], [%1], 16;\n" ::              \
                   "r"(DST), "l"(SRC))
#define CP_COMMIT() asm volatile("cp.async.commit_group;\n")
#define CP_WAIT(N)  asm volatile("cp.async.wait_group %0;\n" ::"n"(N))

// ---------------------------------------------------------------------------
// Precompute kernels
// ---------------------------------------------------------------------------
__global__ void rope_init_kernel() {
  int idx = blockIdx.x * blockDim.x + threadIdx.x;
  if (idx < SEQ * (HD / 2)) {
    int s = idx >> 6;
    int i = idx & 63;
    float inv = (float)pow(10000.0, -(double)(2 * i) / (double)HD);
    float a = (float)s * inv;
    g_cos[idx] = cosf(a);
    g_sin[idx] = sinf(a);
  }
}

// x fp32 -> fp16
__global__ void conv_x_kernel(const float* __restrict__ x) {
  int idx = blockIdx.x * blockDim.x + threadIdx.x;
  if (idx < MROWS * DMODEL) {
    float4 v = *(const float4*)(x + (size_t)idx * 4);
    __half2 a = __floats2half2_rn(v.x, v.y);
    __half2 b = __floats2half2_rn(v.z, v.w);
    *(uint2*)(g_xh + (size_t)idx * 4) =
        make_uint2(*(uint32_t*)&a, *(uint32_t*)&b);
  }
}

// W[k][n] fp32 -> Wt[n][k] fp16 (tiled transpose)
__global__ void tw_kernel(const float* __restrict__ W,
                          __half* __restrict__ Wt, int N) {
  __shared__ float tile[32][33];
  const int n0 = blockIdx.x * 32;
  const int k0 = blockIdx.y * 32;
  const int tx = threadIdx.x;
  const int ty = threadIdx.y;
#pragma unroll
  for (int j = 0; j < 32; j += 8)
    tile[ty + j][tx] = W[(size_t)(k0 + ty + j) * N + n0 + tx];
  __syncthreads();
#pragma unroll
  for (int j = 0; j < 32; j += 8) {
    int n = n0 + ty + j;
    int k = k0 + tx;
    Wt[(size_t)n * DMODEL + k] = __float2half_rn(tile[tx][ty + j]);
  }
}

// ---------------------------------------------------------------------------
// Pipelined fp16 GEMM: C[4096, N] = A[4096, 2048] @ Bt[N, 2048]^T
// Block 128x128, BK=64, 3-stage cp.async, 128 threads = 4 warps (2M x 2N),
// warp tile 64x64.
// MODE 0: merged QKV epilogue (rope etc.)   MODE 3: out proj (fp32)
// ---------------------------------------------------------------------------
#define BK      64
#define STRIDE  72
#define STAGE_H (128 * STRIDE)
#define NITERS  (KBIG / BK)   // 32

template <int MODE>
__global__ __launch_bounds__(128) void gemm_f16_kernel(
    const __half* __restrict__ A, const __half* __restrict__ Bt,
    float* __restrict__ out) {
  extern __shared__ __align__(16) __half smem[];
  __half* As = smem;
  __half* Bs = smem + 3 * STAGE_H;

  const int tid  = threadIdx.x;
  const int wid  = tid >> 5;
  const int lane = tid & 31;
  const int wm   = wid >> 1;   // 0..1
  const int wn   = wid & 1;    // 0..1
  const int g    = lane >> 2;
  const int q4   = lane & 3;
  const int m0   = blockIdx.y * 128;
  const int n0   = blockIdx.x * 128;

  const uint32_t as_base = (uint32_t)__cvta_generic_to_shared(As);
  const uint32_t bs_base = (uint32_t)__cvta_generic_to_shared(Bs);

  const int crow = tid >> 3;   // 0..15
  const int cseg = tid & 7;

  const uint32_t a_off =
      (uint32_t)((wm * 64 + (lane & 15)) * STRIDE + (lane >> 4) * 8) * 2;
  const uint32_t b_off =
      (uint32_t)((wn * 64 + (lane & 7) + ((lane & 16) >> 1)) * STRIDE +
                 (lane & 8)) * 2;

  float c[4][8][4];
#pragma unroll
  for (int mt = 0; mt < 4; mt++)
#pragma unroll
    for (int nt = 0; nt < 8; nt++)
#pragma unroll
      for (int j = 0; j < 4; j++) c[mt][nt][j] = 0.f;

  auto load_stage = [&](int stg, int k0) {
    uint32_t abase = as_base + stg * STAGE_H * 2;
    uint32_t bbase = bs_base + stg * STAGE_H * 2;
#pragma unroll
    for (int j = 0; j < 8; j++) {
      int row = j * 16 + crow;
      uint32_t so = (uint32_t)(row * STRIDE + cseg * 8) * 2;
      CP_ASYNC16(abase + so, A + (size_t)(m0 + row) * KBIG + k0 + cseg * 8);
      CP_ASYNC16(bbase + so, Bt + (size_t)(n0 + row) * KBIG + k0 + cseg * 8);
    }
  };

  load_stage(0, 0);
  CP_COMMIT();
  load_stage(1, BK);
  CP_COMMIT();

  for (int it = 0; it < NITERS; it++) {
    CP_WAIT(1);
    __syncthreads();
    if (it + 2 < NITERS) load_stage((it + 2) % 3, (it + 2) * BK);
    CP_COMMIT();

    const int stg = it % 3;
    const uint32_t ab = as_base + stg * STAGE_H * 2 + a_off;
    const uint32_t bb = bs_base + stg * STAGE_H * 2 + b_off;
#pragma unroll
    for (int kt = 0; kt < 4; kt++) {
      const uint32_t ko = kt * 32;
      uint32_t a[4][4];
#pragma unroll
      for (int mt = 0; mt < 4; mt++)
        LDSM_X4(a[mt][0], a[mt][1], a[mt][2], a[mt][3],
                ab + (uint32_t)(mt * 16 * STRIDE * 2) + ko);
#pragma unroll
      for (int p = 0; p < 4; p++) {
        uint32_t b[4];
        LDSM_X4(b[0], b[1], b[2], b[3],
                bb + (uint32_t)(p * 16 * STRIDE * 2) + ko);
#pragma unroll
        for (int mt = 0; mt < 4; mt++) {
          MMA_16816(c[mt][2 * p],     a[mt], b[0], b[1]);
          MMA_16816(c[mt][2 * p + 1], a[mt], b[2], b[3]);
        }
      }
    }
  }

  // Q scale: 1/sqrt(128) * log2(e) — softmax runs in log2 domain (exp2)
  const float qscale = 0.12753102543684988f;
#pragma unroll
  for (int mt = 0; mt < 4; mt++) {
#pragma unroll
    for (int nt = 0; nt < 8; nt++) {
      int col = n0 + wn * 64 + nt * 8 + q4 * 2;
      int row = m0 + wm * 64 + mt * 16 + g;
      if (MODE == 3) {
        *(float2*)&out[(size_t)row * DMODEL + col] =
            make_float2(c[mt][nt][0], c[mt][nt][1]);
        *(float2*)&out[(size_t)(row + 8) * DMODEL + col] =
            make_float2(c[mt][nt][2], c[mt][nt][3]);
      } else {
#pragma unroll
        for (int hh = 0; hh < 2; hh++) {
          int r = row + hh * 8;
          int b = r >> 11;
          int s = r & 2047;
          float v0 = c[mt][nt][hh * 2];
          float v1 = c[mt][nt][hh * 2 + 1];
          __half* dst;
          if (col < NH * HD) {            // Q: rope + scale (incl. log2e)
            int head = col >> 7, d = col & 127;
            int i    = d >> 1;
            float cs = g_cos[s * 64 + i], sn = g_sin[s * 64 + i];
            float r0 = v0 * cs - v1 * sn, r1 = v0 * sn + v1 * cs;
            v0 = r0 * qscale; v1 = r1 * qscale;
            dst = &g_q[(((size_t)(b * NH + head)) * SEQ + s) * HD + d];
          } else if (col < NH * HD + NKV * HD) {  // K: rope
            int kc = col - NH * HD;
            int head = kc >> 7, d = kc & 127;
            int i    = d >> 1;
            float cs = g_cos[s * 64 + i], sn = g_sin[s * 64 + i];
            float r0 = v0 * cs - v1 * sn, r1 = v0 * sn + v1 * cs;
            v0 = r0; v1 = r1;
            dst = &g_k[(((size_t)(b * NKV + head)) * SEQ + s) * HD + d];
          } else {                        // V
            int vc = col - NH * HD - NKV * HD;
            int head = vc >> 7, d = vc & 127;
            dst = &g_v[(((size_t)(b * NKV + head)) * SEQ + s) * HD + d];
          }
          *(__half2*)dst = __floats2half2_rn(v0, v1);
        }
      }
    }
  }
}

// ---------------------------------------------------------------------------
// Flash attention: 1D grid (heavy q-tiles first), 256 threads/block.
// Double-buffered cp.async K/V chunks of 64 rows. log2-domain softmax (exp2);
// row sums computed by tensor core via ones-column in V smem pad (col 128).
// ---------------------------------------------------------------------------
#define AS_ROW 136                 // halves per smem row
#define ABUF_H (128 * AS_ROW)      // halves per buffer (K rows 0-63, V 64-127)

__global__ __launch_bounds__(256) void attn_kernel(const int* __restrict__ causal_flag) {
  extern __shared__ __align__(16) __half S[];  // [2][128][AS_ROW]

  const int tid  = threadIdx.x;
  const int wid  = tid >> 5;
  const int lane = tid & 31;
  const int g    = lane >> 2;
  const int q4   = lane & 3;
  // Heavy-first schedule: qtile decreasing with block id (causal balance)
  const int bid   = blockIdx.x;
  const int qtile = (SEQ / 128) - 1 - (bid >> 5);
  const int hb    = bid & 31;
  const int h     = hb & 15;
  const int b     = hb >> 4;
  const int kv    = h >> 1;
  const int qbase = qtile * 128;
  const int causal = *causal_flag;

  const uint32_t s_base = (uint32_t)__cvta_generic_to_shared(S);
  const uint32_t q_a = s_base +
      (uint32_t)((wid * 16 + (lane & 15)) * AS_ROW + (lane >> 4) * 8) * 2;
  const uint32_t k_b = s_base +
      (uint32_t)(((lane & 7) + ((lane & 16) >> 1)) * AS_ROW + (lane & 8)) * 2;
  const uint32_t v_b = s_base +
      (uint32_t)((64 + (lane & 15)) * AS_ROW + (lane >> 4) * 8) * 2;
  const uint32_t vs_b = s_base +
      (uint32_t)((64 + (lane & 15)) * AS_ROW + 128) * 2;  // ones column

  // Stage Q tile (128 x 128) into buffer 0 and extract A fragments
  const __half* qp = g_q + (((size_t)(b * NH + h)) * SEQ + qbase) * HD;
#pragma unroll
  for (int j = 0; j < 8; j++) {
    int i   = j * 256 + tid;
    int row = i >> 4;
    int seg = i & 15;
    *(uint4*)&S[row * AS_ROW + seg * 8] = *(const uint4*)(qp + row * HD + seg * 8);
  }
  __syncthreads();
  uint32_t qa[8][4];
#pragma unroll
  for (int kt = 0; kt < 8; kt++)
    LDSM_X4(qa[kt][0], qa[kt][1], qa[kt][2], qa[kt][3], q_a + kt * 32);
  // One-time init of V pad cols 128..135 in BOTH buffers: {1, 0, ..., 0}.
  // cp.async chunk loads never touch these bytes, so they persist.
  if (tid < 128) {
    int buf = tid >> 6;
    int row = 64 + (tid & 63);
    *(uint4*)&S[buf * ABUF_H + row * AS_ROW + 128] =
        make_uint4(pack_half2(1.f, 0.f), 0u, 0u, 0u);
  }
  __syncthreads();  // extractions + pad init done before cp.async overwrites

  float o[16][4];
#pragma unroll
  for (int i = 0; i < 16; i++)
#pragma unroll
    for (int j = 0; j < 4; j++) o[i][j] = 0.f;
  float osum[4] = {0.f, 0.f, 0.f, 0.f};   // tensor-core row sums (col 128)
  float m0 = -1e30f, m1 = -1e30f;

  const int jend = causal ? (qbase + 128) : SEQ;
  const int nchunks = jend >> 6;
  const __half* kbp = g_k + ((size_t)(b * NKV + kv)) * SEQ * HD;
  const __half* vbp = g_v + ((size_t)(b * NKV + kv)) * SEQ * HD;
  const int row0 = qbase + wid * 16 + g;
  const int row1 = row0 + 8;

  const int crow = tid >> 4;   // 0..15
  const int cseg = tid & 15;   // 0..15 -> cseg*8 covers all 128 halves

  auto load_chunk = [&](int stg, int j0) {
    uint32_t base = s_base + (uint32_t)stg * ABUF_H * 2;
#pragma unroll
    for (int j = 0; j < 4; j++) {
      int row = j * 16 + crow;   // 0..63
      uint32_t so = (uint32_t)(row * AS_ROW + cseg * 8) * 2;
      CP_ASYNC16(base + so, kbp + (size_t)(j0 + row) * HD + cseg * 8);
      CP_ASYNC16(base + (uint32_t)(64 * AS_ROW * 2) + so,
                 vbp + (size_t)(j0 + row) * HD + cseg * 8);
    }
  };

  load_chunk(0, 0);
  CP_COMMIT();

  for (int ci = 0; ci < nchunks; ci++) {
    const int j0 = ci * 64;
    CP_WAIT(0);
    __syncthreads();
    if (ci + 1 < nchunks) load_chunk((ci + 1) & 1, j0 + 64);
    CP_COMMIT();

    const uint32_t soff = (uint32_t)(ci & 1) * ABUF_H * 2;

    // S = Q @ K^T : per warp 16 x 64 (scores already in log2 domain)
    float sc[8][4];
#pragma unroll
    for (int i = 0; i < 8; i++)
#pragma unroll
      for (int j = 0; j < 4; j++) sc[i][j] = 0.f;
#pragma unroll
    for (int kt = 0; kt < 8; kt++) {
#pragma unroll
      for (int p = 0; p < 4; p++) {
        uint32_t bf[4];
        LDSM_X4(bf[0], bf[1], bf[2], bf[3],
                k_b + soff + (uint32_t)(p * 16 * AS_ROW * 2) + kt * 32);
        MMA_16816(sc[2 * p],     qa[kt], bf[0], bf[1]);
        MMA_16816(sc[2 * p + 1], qa[kt], bf[2], bf[3]);
      }
    }

    if (causal && j0 + 64 > qbase) {
#pragma unroll
      for (int nt = 0; nt < 8; nt++) {
        int col = j0 + nt * 8 + q4 * 2;
        if (col     > row0) sc[nt][0] = -1e30f;
        if (col + 1 > row0) sc[nt][1] = -1e30f;
        if (col     > row1) sc[nt][2] = -1e30f;
        if (col + 1 > row1) sc[nt][3] = -1e30f;
      }
    }

    float r0 = -1e30f, r1 = -1e30f;
#pragma unroll
    for (int nt = 0; nt < 8; nt++) {
      r0 = fmaxf(r0, fmaxf(sc[nt][0], sc[nt][1]));
      r1 = fmaxf(r1, fmaxf(sc[nt][2], sc[nt][3]));
    }
    r0 = fmaxf(r0, __shfl_xor_sync(0xffffffffu, r0, 1));
    r0 = fmaxf(r0, __shfl_xor_sync(0xffffffffu, r0, 2));
    r1 = fmaxf(r1, __shfl_xor_sync(0xffffffffu, r1, 1));
    r1 = fmaxf(r1, __shfl_xor_sync(0xffffffffu, r1, 2));
    float mn0 = fmaxf(m0, r0), mn1 = fmaxf(m1, r1);
    float sf0 = ex2f(m0 - mn0), sf1 = ex2f(m1 - mn1);
    m0 = mn0; m1 = mn1;
#pragma unroll
    for (int nt = 0; nt < 8; nt++) {
      sc[nt][0] = ex2f(sc[nt][0] - mn0);
      sc[nt][1] = ex2f(sc[nt][1] - mn0);
      sc[nt][2] = ex2f(sc[nt][2] - mn1);
      sc[nt][3] = ex2f(sc[nt][3] - mn1);
    }
#pragma unroll
    for (int i = 0; i < 16; i++) {
      o[i][0] *= sf0; o[i][1] *= sf0;
      o[i][2] *= sf1; o[i][3] *= sf1;
    }
    osum[0] *= sf0; osum[1] *= sf0;
    osum[2] *= sf1; osum[3] *= sf1;

    uint32_t pa[4][4];
#pragma unroll
    for (int kt = 0; kt < 4; kt++) {
      pa[kt][0] = pack_half2(sc[2 * kt][0], sc[2 * kt][1]);
      pa[kt][1] = pack_half2(sc[2 * kt][2], sc[2 * kt][3]);
      pa[kt][2] = pack_half2(sc[2 * kt + 1][0], sc[2 * kt + 1][1]);
      pa[kt][3] = pack_half2(sc[2 * kt + 1][2], sc[2 * kt + 1][3]);
    }

    // O += P @ V ; row sums accumulate via ones-column (col 128) mma
#pragma unroll
    for (int kt = 0; kt < 4; kt++) {
#pragma unroll
      for (int pb = 0; pb < 8; pb++) {
        uint32_t bf[4];
        LDSM_X4_T(bf[0], bf[1], bf[2], bf[3],
                  v_b + soff + (uint32_t)(kt * 16 * AS_ROW * 2) + pb * 32);
        MMA_16816(o[2 * pb],     pa[kt], bf[0], bf[1]);
        MMA_16816(o[2 * pb + 1], pa[kt], bf[2], bf[3]);
      }
      uint32_t sb0, sb1;
      LDSM_X2_T(sb0, sb1, vs_b + soff + (uint32_t)(kt * 16 * AS_ROW * 2));
      MMA_16816(osum, pa[kt], sb0, sb1);
    }
  }

  // Row sums live in q4==0 lanes (col 128 of the 8-col tile) — broadcast.
  float l0 = __shfl_sync(0xffffffffu, osum[0], lane & ~3);
  float l1 = __shfl_sync(0xffffffffu, osum[2], lane & ~3);
  float inv0 = 1.f / l0, inv1 = 1.f / l1;
#pragma unroll
  for (int nt = 0; nt < 16; nt++) {
    int d = nt * 8 + q4 * 2;
#pragma unroll
    for (int hh = 0; hh < 2; hh++) {
      int r = (hh == 0) ? row0 : row1;
      float v0 = o[nt][hh * 2]     * (hh == 0 ? inv0 : inv1);
      float v1 = o[nt][hh * 2 + 1] * (hh == 0 ? inv0 : inv1);
      __half* base = g_oh + (size_t)(b * SEQ + r) * DMODEL + h * HD + d;
      *(__half2*)base = __floats2half2_rn(v0, v1);
    }
  }
}

// ---------------------------------------------------------------------------
// Launch
// ---------------------------------------------------------------------------
extern "C" void kernel_launch(void* const* d_in, const int* in_sizes, int n_in,
                              void* d_out, int out_size) {
  const float* x  = (const float*)d_in[0];
  const float* Wq = (const float*)d_in[1];
  const float* Wk = (const float*)d_in[2];
  const float* Wv = (const float*)d_in[3];
  const float* Wo = (const float*)d_in[4];
  const int* is_causal = (const int*)d_in[5];
  float* out = (float*)d_out;

  __half *xh, *oh, *wt, *wot;
  cudaGetSymbolAddress((void**)&xh,  g_xh);
  cudaGetSymbolAddress((void**)&oh,  g_oh);
  cudaGetSymbolAddress((void**)&wt,  g_wt);
  cudaGetSymbolAddress((void**)&wot, g_wot);

  const int gemm_smem = 6 * STAGE_H * 2;   // 110592
  const int attn_smem = 2 * ABUF_H * 2;    // 69632
  cudaFuncSetAttribute(gemm_f16_kernel<0>,
                       cudaFuncAttributeMaxDynamicSharedMemorySize, gemm_smem);
  cudaFuncSetAttribute(gemm_f16_kernel<3>,
                       cudaFuncAttributeMaxDynamicSharedMemorySize, gemm_smem);
  cudaFuncSetAttribute(attn_kernel,
                       cudaFuncAttributeMaxDynamicSharedMemorySize, attn_smem);

  rope_init_kernel<<<(SEQ * 64 + 255) / 256, 256>>>();
  conv_x_kernel<<<(MROWS * DMODEL / 4) / 256, 256>>>(x);
  tw_kernel<<<dim3((NH * HD) / 32, DMODEL / 32), dim3(32, 8)>>>(
      Wq, wt, NH * HD);
  tw_kernel<<<dim3((NKV * HD) / 32, DMODEL / 32), dim3(32, 8)>>>(
      Wk, wt + (size_t)(NH * HD) * DMODEL, NKV * HD);
  tw_kernel<<<dim3((NKV * HD) / 32, DMODEL / 32), dim3(32, 8)>>>(
      Wv, wt + (size_t)(NH * HD + NKV * HD) * DMODEL, NKV * HD);
  tw_kernel<<<dim3(DMODEL / 32, DMODEL / 32), dim3(32, 8)>>>(Wo, wot, DMODEL);

  gemm_f16_kernel<0><<<dim3(NQKV / 128, MROWS / 128), 128, gemm_smem>>>(
      xh, wt, nullptr);

  attn_kernel<<<(SEQ / 128) * NH * BATCH, 256, attn_smem>>>(is_causal);

  gemm_f16_kernel<3><<<dim3(DMODEL / 128, MROWS / 128), 128, gemm_smem>>>(
      oh, wot, out);
}